// round 4
// baseline (speedup 1.0000x reference)
#include <cuda_runtime.h>
#include <cuda_bf16.h>
#include <cstdint>

#define Bq    2
#define Nseq  2048
#define Cdim  1024
#define Hh    16
#define HDd   64
#define SCALE 0.125f
#define Mrows (Bq*Nseq)

// ---------------- device scratch ----------------
__device__ float         g_q  [(size_t)Bq*Hh*Nseq*HDd];   // fp32, pre-scaled
__device__ __nv_bfloat16 g_kh [(size_t)Bq*Hh*Nseq*HDd];   // K hi  [bh][key][dim]
__device__ __nv_bfloat16 g_kl [(size_t)Bq*Hh*Nseq*HDd];
__device__ __nv_bfloat16 g_vth[(size_t)Bq*Hh*HDd*Nseq];   // V^T hi [bh][dim][key]
__device__ __nv_bfloat16 g_vtl[(size_t)Bq*Hh*HDd*Nseq];
__device__ __nv_bfloat16 g_xh [(size_t)Mrows*Cdim];       // x split
__device__ __nv_bfloat16 g_xl [(size_t)Mrows*Cdim];
__device__ __nv_bfloat16 g_qwh[(size_t)3*Cdim*Cdim];      // qkv_w split
__device__ __nv_bfloat16 g_qwl[(size_t)3*Cdim*Cdim];
__device__ __nv_bfloat16 g_pwh[(size_t)Cdim*Cdim];        // proj_w split
__device__ __nv_bfloat16 g_pwl[(size_t)Cdim*Cdim];
__device__ __nv_bfloat16 g_aoh[(size_t)Mrows*Cdim];       // attn out split
__device__ __nv_bfloat16 g_aol[(size_t)Mrows*Cdim];

// ---------------- helpers ----------------
__device__ __forceinline__ void mma_bf16(float* d, const uint32_t* a, const uint32_t* b)
{
    asm volatile(
        "mma.sync.aligned.m16n8k16.row.col.f32.bf16.bf16.f32 "
        "{%0,%1,%2,%3}, {%4,%5,%6,%7}, {%8,%9}, {%0,%1,%2,%3};"
        : "+f"(d[0]), "+f"(d[1]), "+f"(d[2]), "+f"(d[3])
        : "r"(a[0]), "r"(a[1]), "r"(a[2]), "r"(a[3]), "r"(b[0]), "r"(b[1]));
}

__device__ __forceinline__ void split_pack(float x, float y, uint32_t& h, uint32_t& l)
{
    __nv_bfloat162 hv = __floats2bfloat162_rn(x, y);
    float hx = __bfloat162float(hv.x);
    float hy = __bfloat162float(hv.y);
    __nv_bfloat162 lv = __floats2bfloat162_rn(x - hx, y - hy);
    h = *reinterpret_cast<uint32_t*>(&hv);
    l = *reinterpret_cast<uint32_t*>(&lv);
}

__device__ __forceinline__ uint32_t smem_a(const void* p)
{
    return (uint32_t)__cvta_generic_to_shared(p);
}
__device__ __forceinline__ void cp16(uint32_t dst, const void* src)
{
    asm volatile("cp.async.cg.shared.global [%0], [%1], 16;\n" :: "r"(dst), "l"(src));
}
#define CP_COMMIT() asm volatile("cp.async.commit_group;\n")
template<int N> __device__ __forceinline__ void cp_wait()
{
    asm volatile("cp.async.wait_group %0;\n" :: "n"(N));
}

// ---------------- prep: fp32 -> hi/lo bf16 ----------------
__global__ void convert_split(const float* __restrict__ src,
                              __nv_bfloat16* __restrict__ h,
                              __nv_bfloat16* __restrict__ l, int n2)
{
    int i = blockIdx.x * blockDim.x + threadIdx.x;
    if (i < n2) {
        float2 v = ((const float2*)src)[i];
        uint32_t hh, ll;
        split_pack(v.x, v.y, hh, ll);
        ((uint32_t*)h)[i] = hh;
        ((uint32_t*)l)[i] = ll;
    }
}

// ---------------------------------------------------------------------------
// Split-bf16 GEMM, NT, cp.async 2-stage. BM=BN=128, BK=32, 256 thr (2x4 warps).
// MODE 0: scatter q/k/v.  MODE 1: out + bias.
// ---------------------------------------------------------------------------
#define PADK 20
#define G_ARR (128*PADK)          // u32 per array
#define G_SU  (4*G_ARR)           // u32 per stage
#define GEMM_SMEM (2*G_SU*4)      // bytes = 81920

template<int MODE>
__global__ void __launch_bounds__(256) gemm_mma(
    const __nv_bfloat16* __restrict__ A_h, const __nv_bfloat16* __restrict__ A_l,
    const __nv_bfloat16* __restrict__ W_h, const __nv_bfloat16* __restrict__ W_l,
    const float* __restrict__ bias, float* __restrict__ out)
{
    extern __shared__ uint32_t sm[];

    const int tid  = threadIdx.x;
    const int lane = tid & 31;
    const int warp = tid >> 5;
    const int wm   = warp >> 2;
    const int wn   = warp & 3;
    const int rowBase = blockIdx.y * 128;
    const int colBase = blockIdx.x * 128;

    // staging map: row lr, half lh (16 bf16 = 32B = 2x cp16)
    const int lr = tid >> 1, lh = tid & 1;
    const __nv_bfloat16* pAh = A_h + (size_t)(rowBase + lr) * Cdim + lh*16;
    const __nv_bfloat16* pAl = A_l + (size_t)(rowBase + lr) * Cdim + lh*16;
    const __nv_bfloat16* pWh = W_h + (size_t)(colBase + lr) * Cdim + lh*16;
    const __nv_bfloat16* pWl = W_l + (size_t)(colBase + lr) * Cdim + lh*16;
    const uint32_t dRow = (uint32_t)(lr*PADK + lh*8) * 4;   // byte offset in array
    const uint32_t sbase = smem_a(sm);

    float acc[4][4][4];
#pragma unroll
    for (int mt = 0; mt < 4; mt++)
#pragma unroll
        for (int nt = 0; nt < 4; nt++)
#pragma unroll
            for (int i = 0; i < 4; i++) acc[mt][nt][i] = 0.f;

#define G_ISSUE(s, k0)                                                        \
    do {                                                                      \
        uint32_t b0 = sbase + (uint32_t)(s)*G_SU*4 + dRow;                    \
        cp16(b0,               pAh + (k0));  cp16(b0 + 16,              pAh + (k0) + 8); \
        cp16(b0 + G_ARR*4,     pAl + (k0));  cp16(b0 + G_ARR*4 + 16,    pAl + (k0) + 8); \
        cp16(b0 + 2*G_ARR*4,   pWh + (k0));  cp16(b0 + 2*G_ARR*4 + 16,  pWh + (k0) + 8); \
        cp16(b0 + 3*G_ARR*4,   pWl + (k0));  cp16(b0 + 3*G_ARR*4 + 16,  pWl + (k0) + 8); \
    } while (0)

    G_ISSUE(0, 0);
    CP_COMMIT();

    const int NIT = Cdim / 32;
    for (int it = 0; it < NIT; it++) {
        const int s = it & 1;
        if (it + 1 < NIT) { G_ISSUE(s^1, (it+1)*32); CP_COMMIT(); cp_wait<1>(); }
        else              { cp_wait<0>(); }
        __syncthreads();

        const uint32_t* Ah = sm + s*G_SU;
        const uint32_t* Al = Ah + G_ARR;
        const uint32_t* Wh = Ah + 2*G_ARR;
        const uint32_t* Wl = Ah + 3*G_ARR;

#pragma unroll
        for (int ks = 0; ks < 2; ks++) {
            uint32_t fah[4][4], fal[4][4];
            const int p = ks*8 + (lane & 3);
#pragma unroll
            for (int mt = 0; mt < 4; mt++) {
                const int r = wm*64 + mt*16 + (lane >> 2);
                fah[mt][0] = Ah[r*PADK + p];        fal[mt][0] = Al[r*PADK + p];
                fah[mt][1] = Ah[(r+8)*PADK + p];    fal[mt][1] = Al[(r+8)*PADK + p];
                fah[mt][2] = Ah[r*PADK + p + 4];    fal[mt][2] = Al[r*PADK + p + 4];
                fah[mt][3] = Ah[(r+8)*PADK + p+4];  fal[mt][3] = Al[(r+8)*PADK + p+4];
            }
#pragma unroll
            for (int nt = 0; nt < 4; nt++) {
                const int n = wn*32 + nt*8 + (lane >> 2);
                uint32_t bh2[2] = { Wh[n*PADK + p], Wh[n*PADK + p + 4] };
                uint32_t bl2[2] = { Wl[n*PADK + p], Wl[n*PADK + p + 4] };
#pragma unroll
                for (int mt = 0; mt < 4; mt++) {
                    mma_bf16(acc[mt][nt], fah[mt], bh2);
                    mma_bf16(acc[mt][nt], fah[mt], bl2);
                    mma_bf16(acc[mt][nt], fal[mt], bh2);
                }
            }
        }
        __syncthreads();
    }
#undef G_ISSUE

    // epilogue
#pragma unroll
    for (int mt = 0; mt < 4; mt++) {
#pragma unroll
        for (int nt = 0; nt < 4; nt++) {
            const int r0 = rowBase + wm*64 + mt*16 + (lane >> 2);
            const int cc = colBase + wn*32 + nt*8 + 2*(lane & 3);
            if (MODE == 1) {
                float b0 = bias[cc], b1 = bias[cc+1];
                *(float2*)(out + (size_t)r0*Cdim + cc) =
                    make_float2(acc[mt][nt][0] + b0, acc[mt][nt][1] + b1);
                *(float2*)(out + (size_t)(r0+8)*Cdim + cc) =
                    make_float2(acc[mt][nt][2] + b0, acc[mt][nt][3] + b1);
            } else {
#pragma unroll
                for (int half = 0; half < 2; half++) {
                    const int m  = r0 + half*8;
                    const float v0 = acc[mt][nt][half*2 + 0];
                    const float v1 = acc[mt][nt][half*2 + 1];
                    const int bb = m >> 11, n = m & (Nseq-1);
                    const int which = cc >> 10, c = cc & (Cdim-1);
                    const int hh = c >> 6, d = c & 63;
                    const size_t bh = (size_t)bb*Hh + hh;
                    if (which == 0) {
                        const size_t idx = (bh*Nseq + n)*HDd + d;
                        *(float2*)(g_q + idx) = make_float2(v0*SCALE, v1*SCALE);
                    } else if (which == 1) {
                        const size_t idx = (bh*Nseq + n)*HDd + d;
                        uint32_t h, l;
                        split_pack(v0, v1, h, l);
                        *(uint32_t*)(g_kh + idx) = h;
                        *(uint32_t*)(g_kl + idx) = l;
                    } else {
                        const size_t idx = (bh*HDd + d)*Nseq + n;  // transposed
                        __nv_bfloat162 hv = __floats2bfloat162_rn(v0, v1);
                        float l0 = v0 - __bfloat162float(hv.x);
                        float l1 = v1 - __bfloat162float(hv.y);
                        __nv_bfloat162 lv = __floats2bfloat162_rn(l0, l1);
                        g_vth[idx]        = hv.x;  g_vtl[idx]        = lv.x;
                        g_vth[idx + Nseq] = hv.y;  g_vtl[idx + Nseq] = lv.y;
                    }
                }
            }
        }
    }
}

// ---------------------------------------------------------------------------
// Flash attention, split-bf16 mma, cp.async 2-stage (K/V hi/lo + alibi + mask).
// Grid: (N/64, B*H). Block: 128 (4 warps). Warp w owns query rows [w*16,+16).
// ---------------------------------------------------------------------------
#define PADA 36
#define A_KV   (64*PADA)                       // u32 per K/V array
#define A_ALI  (64*68)                         // f32 alibi tile
#define A_SU   (4*A_KV + A_ALI + 64)           // u32 per stage = 13632
#define ATTN_SMEM (2*A_SU*4)                   // 109056 bytes

__global__ void __launch_bounds__(128) attn_mma(
    const float* __restrict__ alibi, const int* __restrict__ pmask)
{
    extern __shared__ uint32_t sm[];

    const int tid  = threadIdx.x;
    const int lane = tid & 31;
    const int warp = tid >> 5;
    const int bh   = blockIdx.y;
    const int b    = bh >> 4;
    const int h    = bh & 15;
    const int q0   = blockIdx.x * 64;

    const int r0 = warp*16 + (lane >> 2);
    const int c2 = 2*(lane & 3);

    // Q fragments, register-resident
    uint32_t qh[4][4], ql[4][4];
    {
        const float* qbase = g_q + ((size_t)bh*Nseq + q0)*HDd;
#pragma unroll
        for (int ks = 0; ks < 4; ks++) {
            const float* p0 = qbase + (size_t)r0*HDd + ks*16 + c2;
            const float* p1 = p0 + 8*HDd;
            float2 e0 = *(const float2*)p0;
            float2 e1 = *(const float2*)p1;
            float2 e2 = *(const float2*)(p0 + 8);
            float2 e3 = *(const float2*)(p1 + 8);
            split_pack(e0.x, e0.y, qh[ks][0], ql[ks][0]);
            split_pack(e1.x, e1.y, qh[ks][1], ql[ks][1]);
            split_pack(e2.x, e2.y, qh[ks][2], ql[ks][2]);
            split_pack(e3.x, e3.y, qh[ks][3], ql[ks][3]);
        }
    }

    float o[8][4];
#pragma unroll
    for (int dt = 0; dt < 8; dt++)
#pragma unroll
        for (int i = 0; i < 4; i++) o[dt][i] = 0.f;
    float m0 = -1e30f, m1 = -1e30f, l0 = 0.f, l1 = 0.f;

    const __nv_bfloat16* kh_g = g_kh  + (size_t)bh*Nseq*HDd;
    const __nv_bfloat16* kl_g = g_kl  + (size_t)bh*Nseq*HDd;
    const __nv_bfloat16* vh_g = g_vth + (size_t)bh*HDd*Nseq;
    const __nv_bfloat16* vl_g = g_vtl + (size_t)bh*HDd*Nseq;
    const float*         ab   = alibi + ((size_t)bh*Nseq + q0)*Nseq;
    const int*           pm   = pmask + (size_t)b*Nseq;

    const uint32_t sbase = smem_a(sm);
    const int sr = tid >> 1;          // 0..63 staging row
    const int sq = tid & 1;           // quarter

#define A_ISSUE(s, k0)                                                         \
    do {                                                                       \
        const uint32_t st = sbase + (uint32_t)(s)*A_SU*4;                      \
        const uint32_t rb = (uint32_t)(sr*PADA + sq*16)*4;                     \
        const __nv_bfloat16* k_h = kh_g + (size_t)((k0) + sr)*HDd + sq*32;     \
        const __nv_bfloat16* k_l = kl_g + (size_t)((k0) + sr)*HDd + sq*32;     \
        const __nv_bfloat16* v_h = vh_g + (size_t)sr*Nseq + (k0) + sq*32;      \
        const __nv_bfloat16* v_l = vl_g + (size_t)sr*Nseq + (k0) + sq*32;      \
        _Pragma("unroll")                                                      \
        for (int j = 0; j < 4; j++) {                                          \
            cp16(st + rb            + j*16, k_h + j*8);                        \
            cp16(st + A_KV*4   + rb + j*16, k_l + j*8);                        \
            cp16(st + 2*A_KV*4 + rb + j*16, v_h + j*8);                        \
            cp16(st + 3*A_KV*4 + rb + j*16, v_l + j*8);                        \
        }                                                                      \
        const uint32_t ao = st + 4*A_KV*4 + (uint32_t)(sr*68 + sq*32)*4;       \
        const float* asrc = ab + (size_t)sr*Nseq + (k0) + sq*32;               \
        _Pragma("unroll")                                                      \
        for (int j = 0; j < 8; j++) cp16(ao + j*16, asrc + j*4);               \
        if (tid < 16)                                                          \
            cp16(st + (4*A_KV + A_ALI)*4 + tid*16, pm + (k0) + tid*4);         \
    } while (0)

    A_ISSUE(0, 0);
    CP_COMMIT();

    for (int it = 0; it < Nseq/64; it++) {
        const int s  = it & 1;
        const int k0 = it * 64;
        if (it + 1 < Nseq/64) { A_ISSUE(s^1, (it+1)*64); CP_COMMIT(); cp_wait<1>(); }
        else                  { cp_wait<0>(); }
        __syncthreads();

        const uint32_t* Kh = sm + s*A_SU;
        const uint32_t* Kl = Kh + A_KV;
        const uint32_t* Vh = Kh + 2*A_KV;
        const uint32_t* Vl = Kh + 3*A_KV;
        const float*    Ps = (const float*)(Kh + 4*A_KV);
        const int*      Mk = (const int*)(Kh + 4*A_KV + A_ALI);

        // S = Q K^T
        float sacc[8][4];
#pragma unroll
        for (int nt = 0; nt < 8; nt++)
#pragma unroll
            for (int i = 0; i < 4; i++) sacc[nt][i] = 0.f;
#pragma unroll
        for (int ks = 0; ks < 4; ks++) {
            const int p = ks*8 + (lane & 3);
#pragma unroll
            for (int nt = 0; nt < 8; nt++) {
                const int key = nt*8 + (lane >> 2);
                uint32_t bh2[2] = { Kh[key*PADA + p], Kh[key*PADA + p + 4] };
                uint32_t bl2[2] = { Kl[key*PADA + p], Kl[key*PADA + p + 4] };
                mma_bf16(sacc[nt], qh[ks], bh2);
                mma_bf16(sacc[nt], qh[ks], bl2);
                mma_bf16(sacc[nt], ql[ks], bh2);
            }
        }

        // + alibi + mask (from smem, prefetched)
#pragma unroll
        for (int nt = 0; nt < 8; nt++) {
            const int kc = nt*8 + c2;
            float2 a0 = *(const float2*)(Ps + r0*68 + kc);
            float2 a1 = *(const float2*)(Ps + (r0+8)*68 + kc);
            const float mk0 = Mk[kc]   ? -1e30f : 0.f;
            const float mk1 = Mk[kc+1] ? -1e30f : 0.f;
            sacc[nt][0] += a0.x + mk0;  sacc[nt][1] += a0.y + mk1;
            sacc[nt][2] += a1.x + mk0;  sacc[nt][3] += a1.y + mk1;
        }

        // online softmax
        float mx0 = -1e30f, mx1 = -1e30f;
#pragma unroll
        for (int nt = 0; nt < 8; nt++) {
            mx0 = fmaxf(mx0, fmaxf(sacc[nt][0], sacc[nt][1]));
            mx1 = fmaxf(mx1, fmaxf(sacc[nt][2], sacc[nt][3]));
        }
        mx0 = fmaxf(mx0, __shfl_xor_sync(0xffffffffu, mx0, 1));
        mx0 = fmaxf(mx0, __shfl_xor_sync(0xffffffffu, mx0, 2));
        mx1 = fmaxf(mx1, __shfl_xor_sync(0xffffffffu, mx1, 1));
        mx1 = fmaxf(mx1, __shfl_xor_sync(0xffffffffu, mx1, 2));

        const float mn0 = fmaxf(m0, mx0), mn1 = fmaxf(m1, mx1);
        const float cr0 = __expf(m0 - mn0), cr1 = __expf(m1 - mn1);
        float ls0 = 0.f, ls1 = 0.f;
#pragma unroll
        for (int nt = 0; nt < 8; nt++) {
            sacc[nt][0] = __expf(sacc[nt][0] - mn0);
            sacc[nt][1] = __expf(sacc[nt][1] - mn0);
            sacc[nt][2] = __expf(sacc[nt][2] - mn1);
            sacc[nt][3] = __expf(sacc[nt][3] - mn1);
            ls0 += sacc[nt][0] + sacc[nt][1];
            ls1 += sacc[nt][2] + sacc[nt][3];
        }
        ls0 += __shfl_xor_sync(0xffffffffu, ls0, 1);
        ls0 += __shfl_xor_sync(0xffffffffu, ls0, 2);
        ls1 += __shfl_xor_sync(0xffffffffu, ls1, 1);
        ls1 += __shfl_xor_sync(0xffffffffu, ls1, 2);
        l0 = l0*cr0 + ls0;  l1 = l1*cr1 + ls1;
        m0 = mn0;           m1 = mn1;

#pragma unroll
        for (int dt = 0; dt < 8; dt++) {
            o[dt][0] *= cr0; o[dt][1] *= cr0;
            o[dt][2] *= cr1; o[dt][3] *= cr1;
        }

        // O += P V
#pragma unroll
        for (int pk = 0; pk < 4; pk++) {
            uint32_t pa_h[4], pa_l[4];
            split_pack(sacc[2*pk][0],   sacc[2*pk][1],   pa_h[0], pa_l[0]);
            split_pack(sacc[2*pk][2],   sacc[2*pk][3],   pa_h[1], pa_l[1]);
            split_pack(sacc[2*pk+1][0], sacc[2*pk+1][1], pa_h[2], pa_l[2]);
            split_pack(sacc[2*pk+1][2], sacc[2*pk+1][3], pa_h[3], pa_l[3]);
            const int p = pk*8 + (lane & 3);
#pragma unroll
            for (int dt = 0; dt < 8; dt++) {
                const int dim = dt*8 + (lane >> 2);
                uint32_t vb_h[2] = { Vh[dim*PADA + p], Vh[dim*PADA + p + 4] };
                uint32_t vb_l[2] = { Vl[dim*PADA + p], Vl[dim*PADA + p + 4] };
                mma_bf16(o[dt], pa_h, vb_h);
                mma_bf16(o[dt], pa_h, vb_l);
                mma_bf16(o[dt], pa_l, vb_h);
            }
        }
        __syncthreads();
    }
#undef A_ISSUE

    // finalize: write hi/lo bf16 directly (feeds proj GEMM)
    const float inv0 = (l0 > 0.f) ? (1.f/l0) : 0.f;
    const float inv1 = (l1 > 0.f) ? (1.f/l1) : 0.f;
    const size_t i0 = ((size_t)b*Nseq + q0 + r0)*Cdim + h*HDd;
    const size_t i1 = i0 + (size_t)8*Cdim;
#pragma unroll
    for (int dt = 0; dt < 8; dt++) {
        uint32_t hh, ll;
        split_pack(o[dt][0]*inv0, o[dt][1]*inv0, hh, ll);
        *(uint32_t*)(g_aoh + i0 + dt*8 + c2) = hh;
        *(uint32_t*)(g_aol + i0 + dt*8 + c2) = ll;
        split_pack(o[dt][2]*inv1, o[dt][3]*inv1, hh, ll);
        *(uint32_t*)(g_aoh + i1 + dt*8 + c2) = hh;
        *(uint32_t*)(g_aol + i1 + dt*8 + c2) = ll;
    }
}

// ---------------------------------------------------------------------------
extern "C" void kernel_launch(void* const* d_in, const int* in_sizes, int n_in,
                              void* d_out, int out_size)
{
    const float* x      = (const float*)d_in[0];
    const int*   pmask  = (const int*)d_in[1];
    const float* alibi  = (const float*)d_in[2];
    const float* qkv_w  = (const float*)d_in[3];
    const float* proj_w = (const float*)d_in[4];
    const float* proj_b = (const float*)d_in[5];
    float*       out    = (float*)d_out;

    static int inited = 0;
    if (!inited) {
        cudaFuncSetAttribute(gemm_mma<0>, cudaFuncAttributeMaxDynamicSharedMemorySize, GEMM_SMEM);
        cudaFuncSetAttribute(gemm_mma<1>, cudaFuncAttributeMaxDynamicSharedMemorySize, GEMM_SMEM);
        cudaFuncSetAttribute(attn_mma,    cudaFuncAttributeMaxDynamicSharedMemorySize, ATTN_SMEM);
        inited = 1;
    }

    __nv_bfloat16 *xh, *xl, *qwh, *qwl, *pwh, *pwl, *aoh, *aol;
    cudaGetSymbolAddress((void**)&xh,  g_xh);  cudaGetSymbolAddress((void**)&xl,  g_xl);
    cudaGetSymbolAddress((void**)&qwh, g_qwh); cudaGetSymbolAddress((void**)&qwl, g_qwl);
    cudaGetSymbolAddress((void**)&pwh, g_pwh); cudaGetSymbolAddress((void**)&pwl, g_pwl);
    cudaGetSymbolAddress((void**)&aoh, g_aoh); cudaGetSymbolAddress((void**)&aol, g_aol);

    // 0) pre-split inputs/weights
    convert_split<<<(Mrows*Cdim/2 + 255)/256, 256>>>(x,      xh,  xl,  Mrows*Cdim/2);
    convert_split<<<(3*Cdim*Cdim/2 + 255)/256, 256>>>(qkv_w, qwh, qwl, 3*Cdim*Cdim/2);
    convert_split<<<(Cdim*Cdim/2 + 255)/256, 256>>>(proj_w,  pwh, pwl, Cdim*Cdim/2);

    // 1) QKV projection
    gemm_mma<0><<<dim3(24, 32), 256, GEMM_SMEM>>>(xh, xl, qwh, qwl, nullptr, nullptr);

    // 2) attention
    attn_mma<<<dim3(Nseq/64, Bq*Hh), 128, ATTN_SMEM>>>(alibi, pmask);

    // 3) output projection
    gemm_mma<1><<<dim3(8, 32), 256, GEMM_SMEM>>>(aoh, aol, pwh, pwl, proj_b, out);
}

// round 5
// speedup vs baseline: 1.3093x; 1.3093x over previous
#include <cuda_runtime.h>
#include <cuda_bf16.h>
#include <cstdint>

#define Bq    2
#define Nseq  2048
#define Cdim  1024
#define Hh    16
#define HDd   64
#define SCALE 0.125f
#define Mrows (Bq*Nseq)

// ---------------- device scratch ----------------
__device__ float         g_q  [(size_t)Bq*Hh*Nseq*HDd];   // fp32, pre-scaled
__device__ __nv_bfloat16 g_kh [(size_t)Bq*Hh*Nseq*HDd];   // K hi  [bh][key][dim]
__device__ __nv_bfloat16 g_kl [(size_t)Bq*Hh*Nseq*HDd];
__device__ __nv_bfloat16 g_vth[(size_t)Bq*Hh*HDd*Nseq];   // V^T hi [bh][dim][key]
__device__ __nv_bfloat16 g_vtl[(size_t)Bq*Hh*HDd*Nseq];
__device__ __nv_bfloat16 g_xh [(size_t)Mrows*Cdim];
__device__ __nv_bfloat16 g_xl [(size_t)Mrows*Cdim];
__device__ __nv_bfloat16 g_qwh[(size_t)3*Cdim*Cdim];
__device__ __nv_bfloat16 g_qwl[(size_t)3*Cdim*Cdim];
__device__ __nv_bfloat16 g_pwh[(size_t)Cdim*Cdim];
__device__ __nv_bfloat16 g_pwl[(size_t)Cdim*Cdim];
__device__ __nv_bfloat16 g_aoh[(size_t)Mrows*Cdim];
__device__ __nv_bfloat16 g_aol[(size_t)Mrows*Cdim];

// ---------------- helpers ----------------
__device__ __forceinline__ void mma_bf16(float* d, const uint32_t* a, const uint32_t* b)
{
    asm volatile(
        "mma.sync.aligned.m16n8k16.row.col.f32.bf16.bf16.f32 "
        "{%0,%1,%2,%3}, {%4,%5,%6,%7}, {%8,%9}, {%0,%1,%2,%3};"
        : "+f"(d[0]), "+f"(d[1]), "+f"(d[2]), "+f"(d[3])
        : "r"(a[0]), "r"(a[1]), "r"(a[2]), "r"(a[3]), "r"(b[0]), "r"(b[1]));
}

__device__ __forceinline__ void split_pack(float x, float y, uint32_t& h, uint32_t& l)
{
    __nv_bfloat162 hv = __floats2bfloat162_rn(x, y);
    float hx = __bfloat162float(hv.x);
    float hy = __bfloat162float(hv.y);
    __nv_bfloat162 lv = __floats2bfloat162_rn(x - hx, y - hy);
    h = *reinterpret_cast<uint32_t*>(&hv);
    l = *reinterpret_cast<uint32_t*>(&lv);
}

__device__ __forceinline__ uint32_t smem_a(const void* p)
{
    return (uint32_t)__cvta_generic_to_shared(p);
}
__device__ __forceinline__ void cp16(uint32_t dst, const void* src)
{
    asm volatile("cp.async.cg.shared.global [%0], [%1], 16;\n" :: "r"(dst), "l"(src));
}
#define CP_COMMIT() asm volatile("cp.async.commit_group;\n")
template<int N> __device__ __forceinline__ void cp_wait()
{
    asm volatile("cp.async.wait_group %0;\n" :: "n"(N));
}

// ---------------- prep: fp32 -> hi/lo bf16 ----------------
__global__ void convert_split(const float* __restrict__ src,
                              __nv_bfloat16* __restrict__ h,
                              __nv_bfloat16* __restrict__ l, int n2)
{
    int i = blockIdx.x * blockDim.x + threadIdx.x;
    if (i < n2) {
        float2 v = ((const float2*)src)[i];
        uint32_t hh, ll;
        split_pack(v.x, v.y, hh, ll);
        ((uint32_t*)h)[i] = hh;
        ((uint32_t*)l)[i] = ll;
    }
}

// ---------------------------------------------------------------------------
// Split-bf16 GEMM, NT, cp.async 2-stage. BM=BN=128, BK=32, 256 thr (2x4 warps).
// __launch_bounds__(256,2): cap regs at 128 so 2 CTAs/SM fit the register file.
// ---------------------------------------------------------------------------
#define PADK 20
#define G_ARR (128*PADK)
#define G_SU  (4*G_ARR)
#define GEMM_SMEM (2*G_SU*4)

template<int MODE>
__global__ void __launch_bounds__(256, 2) gemm_mma(
    const __nv_bfloat16* __restrict__ A_h, const __nv_bfloat16* __restrict__ A_l,
    const __nv_bfloat16* __restrict__ W_h, const __nv_bfloat16* __restrict__ W_l,
    const float* __restrict__ bias, float* __restrict__ out)
{
    extern __shared__ uint32_t sm[];

    const int tid  = threadIdx.x;
    const int lane = tid & 31;
    const int warp = tid >> 5;
    const int wm   = warp >> 2;
    const int wn   = warp & 3;
    const int rowBase = blockIdx.y * 128;
    const int colBase = blockIdx.x * 128;

    const int lr = tid >> 1, lh = tid & 1;
    const __nv_bfloat16* pAh = A_h + (size_t)(rowBase + lr) * Cdim + lh*16;
    const __nv_bfloat16* pAl = A_l + (size_t)(rowBase + lr) * Cdim + lh*16;
    const __nv_bfloat16* pWh = W_h + (size_t)(colBase + lr) * Cdim + lh*16;
    const __nv_bfloat16* pWl = W_l + (size_t)(colBase + lr) * Cdim + lh*16;
    const uint32_t dRow = (uint32_t)(lr*PADK + lh*8) * 4;
    const uint32_t sbase = smem_a(sm);

    float acc[4][4][4];
#pragma unroll
    for (int mt = 0; mt < 4; mt++)
#pragma unroll
        for (int nt = 0; nt < 4; nt++)
#pragma unroll
            for (int i = 0; i < 4; i++) acc[mt][nt][i] = 0.f;

#define G_ISSUE(s, k0)                                                        \
    do {                                                                      \
        uint32_t b0 = sbase + (uint32_t)(s)*G_SU*4 + dRow;                    \
        cp16(b0,               pAh + (k0));  cp16(b0 + 16,              pAh + (k0) + 8); \
        cp16(b0 + G_ARR*4,     pAl + (k0));  cp16(b0 + G_ARR*4 + 16,    pAl + (k0) + 8); \
        cp16(b0 + 2*G_ARR*4,   pWh + (k0));  cp16(b0 + 2*G_ARR*4 + 16,  pWh + (k0) + 8); \
        cp16(b0 + 3*G_ARR*4,   pWl + (k0));  cp16(b0 + 3*G_ARR*4 + 16,  pWl + (k0) + 8); \
    } while (0)

    G_ISSUE(0, 0);
    CP_COMMIT();

    const int NIT = Cdim / 32;
    for (int it = 0; it < NIT; it++) {
        const int s = it & 1;
        if (it + 1 < NIT) { G_ISSUE(s^1, (it+1)*32); CP_COMMIT(); cp_wait<1>(); }
        else              { cp_wait<0>(); }
        __syncthreads();

        const uint32_t* Ah = sm + s*G_SU;
        const uint32_t* Al = Ah + G_ARR;
        const uint32_t* Wh = Ah + 2*G_ARR;
        const uint32_t* Wl = Ah + 3*G_ARR;

#pragma unroll
        for (int ks = 0; ks < 2; ks++) {
            uint32_t fah[4][4], fal[4][4];
            const int p = ks*8 + (lane & 3);
#pragma unroll
            for (int mt = 0; mt < 4; mt++) {
                const int r = wm*64 + mt*16 + (lane >> 2);
                fah[mt][0] = Ah[r*PADK + p];        fal[mt][0] = Al[r*PADK + p];
                fah[mt][1] = Ah[(r+8)*PADK + p];    fal[mt][1] = Al[(r+8)*PADK + p];
                fah[mt][2] = Ah[r*PADK + p + 4];    fal[mt][2] = Al[r*PADK + p + 4];
                fah[mt][3] = Ah[(r+8)*PADK + p+4];  fal[mt][3] = Al[(r+8)*PADK + p+4];
            }
#pragma unroll
            for (int nt = 0; nt < 4; nt++) {
                const int n = wn*32 + nt*8 + (lane >> 2);
                uint32_t bh2[2] = { Wh[n*PADK + p], Wh[n*PADK + p + 4] };
                uint32_t bl2[2] = { Wl[n*PADK + p], Wl[n*PADK + p + 4] };
#pragma unroll
                for (int mt = 0; mt < 4; mt++) {
                    mma_bf16(acc[mt][nt], fah[mt], bh2);
                    mma_bf16(acc[mt][nt], fah[mt], bl2);
                    mma_bf16(acc[mt][nt], fal[mt], bh2);
                }
            }
        }
        __syncthreads();
    }
#undef G_ISSUE

    // epilogue
#pragma unroll
    for (int mt = 0; mt < 4; mt++) {
#pragma unroll
        for (int nt = 0; nt < 4; nt++) {
            const int r0 = rowBase + wm*64 + mt*16 + (lane >> 2);
            const int cc = colBase + wn*32 + nt*8 + 2*(lane & 3);
            if (MODE == 1) {
                float b0 = bias[cc], b1 = bias[cc+1];
                *(float2*)(out + (size_t)r0*Cdim + cc) =
                    make_float2(acc[mt][nt][0] + b0, acc[mt][nt][1] + b1);
                *(float2*)(out + (size_t)(r0+8)*Cdim + cc) =
                    make_float2(acc[mt][nt][2] + b0, acc[mt][nt][3] + b1);
            } else {
#pragma unroll
                for (int half = 0; half < 2; half++) {
                    const int m  = r0 + half*8;
                    const float v0 = acc[mt][nt][half*2 + 0];
                    const float v1 = acc[mt][nt][half*2 + 1];
                    const int bb = m >> 11, n = m & (Nseq-1);
                    const int which = cc >> 10, c = cc & (Cdim-1);
                    const int hh = c >> 6, d = c & 63;
                    const size_t bh = (size_t)bb*Hh + hh;
                    if (which == 0) {
                        const size_t idx = (bh*Nseq + n)*HDd + d;
                        *(float2*)(g_q + idx) = make_float2(v0*SCALE, v1*SCALE);
                    } else if (which == 1) {
                        const size_t idx = (bh*Nseq + n)*HDd + d;
                        uint32_t h, l;
                        split_pack(v0, v1, h, l);
                        *(uint32_t*)(g_kh + idx) = h;
                        *(uint32_t*)(g_kl + idx) = l;
                    } else {
                        const size_t idx = (bh*HDd + d)*Nseq + n;  // transposed
                        __nv_bfloat162 hv = __floats2bfloat162_rn(v0, v1);
                        float l0 = v0 - __bfloat162float(hv.x);
                        float l1 = v1 - __bfloat162float(hv.y);
                        __nv_bfloat162 lv = __floats2bfloat162_rn(l0, l1);
                        g_vth[idx]        = hv.x;  g_vtl[idx]        = lv.x;
                        g_vth[idx + Nseq] = hv.y;  g_vtl[idx + Nseq] = lv.y;
                    }
                }
            }
        }
    }
}

// ---------------------------------------------------------------------------
// Flash attention, split-bf16 mma, cp.async 2-stage K/V+mask (37KB/stage).
// ALiBi: direct LDG into registers, issued before the S mma chain.
// Grid: (N/64, B*H). Block: 128 (4 warps), min 3 CTAs/SM.
// ---------------------------------------------------------------------------
#define PADA 36
#define A_KV   (64*PADA)                 // u32 per K/V array
#define A_SU   (4*A_KV + 64)             // u32 per stage (incl. mask)
#define ATTN_SMEM (2*A_SU*4)             // 74240 bytes

__global__ void __launch_bounds__(128, 3) attn_mma(
    const float* __restrict__ alibi, const int* __restrict__ pmask)
{
    extern __shared__ uint32_t sm[];

    const int tid  = threadIdx.x;
    const int lane = tid & 31;
    const int warp = tid >> 5;
    const int bh   = blockIdx.y;
    const int b    = bh >> 4;
    const int h    = bh & 15;
    const int q0   = blockIdx.x * 64;

    const int r0 = warp*16 + (lane >> 2);
    const int c2 = 2*(lane & 3);

    // Q fragments, register-resident
    uint32_t qh[4][4], ql[4][4];
    {
        const float* qbase = g_q + ((size_t)bh*Nseq + q0)*HDd;
#pragma unroll
        for (int ks = 0; ks < 4; ks++) {
            const float* p0 = qbase + (size_t)r0*HDd + ks*16 + c2;
            const float* p1 = p0 + 8*HDd;
            float2 e0 = *(const float2*)p0;
            float2 e1 = *(const float2*)p1;
            float2 e2 = *(const float2*)(p0 + 8);
            float2 e3 = *(const float2*)(p1 + 8);
            split_pack(e0.x, e0.y, qh[ks][0], ql[ks][0]);
            split_pack(e1.x, e1.y, qh[ks][1], ql[ks][1]);
            split_pack(e2.x, e2.y, qh[ks][2], ql[ks][2]);
            split_pack(e3.x, e3.y, qh[ks][3], ql[ks][3]);
        }
    }

    float o[8][4];
#pragma unroll
    for (int dt = 0; dt < 8; dt++)
#pragma unroll
        for (int i = 0; i < 4; i++) o[dt][i] = 0.f;
    float m0 = -1e30f, m1 = -1e30f, l0 = 0.f, l1 = 0.f;

    const __nv_bfloat16* kh_g = g_kh  + (size_t)bh*Nseq*HDd;
    const __nv_bfloat16* kl_g = g_kl  + (size_t)bh*Nseq*HDd;
    const __nv_bfloat16* vh_g = g_vth + (size_t)bh*HDd*Nseq;
    const __nv_bfloat16* vl_g = g_vtl + (size_t)bh*HDd*Nseq;
    const float*         ab   = alibi + ((size_t)bh*Nseq + q0)*Nseq;
    const int*           pm   = pmask + (size_t)b*Nseq;

    const uint32_t sbase = smem_a(sm);
    const int sr = tid >> 1;
    const int sq = tid & 1;

#define A_ISSUE(s, k0)                                                         \
    do {                                                                       \
        const uint32_t st = sbase + (uint32_t)(s)*A_SU*4;                      \
        const uint32_t rb = (uint32_t)(sr*PADA + sq*16)*4;                     \
        const __nv_bfloat16* k_h = kh_g + (size_t)((k0) + sr)*HDd + sq*32;     \
        const __nv_bfloat16* k_l = kl_g + (size_t)((k0) + sr)*HDd + sq*32;     \
        const __nv_bfloat16* v_h = vh_g + (size_t)sr*Nseq + (k0) + sq*32;      \
        const __nv_bfloat16* v_l = vl_g + (size_t)sr*Nseq + (k0) + sq*32;      \
        _Pragma("unroll")                                                      \
        for (int j = 0; j < 4; j++) {                                          \
            cp16(st + rb            + j*16, k_h + j*8);                        \
            cp16(st + A_KV*4   + rb + j*16, k_l + j*8);                        \
            cp16(st + 2*A_KV*4 + rb + j*16, v_h + j*8);                        \
            cp16(st + 3*A_KV*4 + rb + j*16, v_l + j*8);                        \
        }                                                                      \
        if (tid < 16)                                                          \
            cp16(st + 4*A_KV*4 + tid*16, pm + (k0) + tid*4);                   \
    } while (0)

    A_ISSUE(0, 0);
    CP_COMMIT();

    for (int it = 0; it < Nseq/64; it++) {
        const int s  = it & 1;
        const int k0 = it * 64;
        if (it + 1 < Nseq/64) { A_ISSUE(s^1, (it+1)*64); CP_COMMIT(); cp_wait<1>(); }
        else                  { cp_wait<0>(); }
        __syncthreads();

        const uint32_t* Kh = sm + s*A_SU;
        const uint32_t* Kl = Kh + A_KV;
        const uint32_t* Vh = Kh + 2*A_KV;
        const uint32_t* Vl = Kh + 3*A_KV;
        const int*      Mk = (const int*)(Kh + 4*A_KV);

        // issue ALiBi LDGs early: they land while the S mma chain runs
        float2 ali0[8], ali1[8];
#pragma unroll
        for (int nt = 0; nt < 8; nt++) {
            const int kc = nt*8 + c2;
            ali0[nt] = *(const float2*)(ab + (size_t)r0*Nseq + k0 + kc);
            ali1[nt] = *(const float2*)(ab + (size_t)(r0+8)*Nseq + k0 + kc);
        }

        // S = Q K^T
        float sacc[8][4];
#pragma unroll
        for (int nt = 0; nt < 8; nt++)
#pragma unroll
            for (int i = 0; i < 4; i++) sacc[nt][i] = 0.f;
#pragma unroll
        for (int ks = 0; ks < 4; ks++) {
            const int p = ks*8 + (lane & 3);
#pragma unroll
            for (int nt = 0; nt < 8; nt++) {
                const int key = nt*8 + (lane >> 2);
                uint32_t bh2[2] = { Kh[key*PADA + p], Kh[key*PADA + p + 4] };
                uint32_t bl2[2] = { Kl[key*PADA + p], Kl[key*PADA + p + 4] };
                mma_bf16(sacc[nt], qh[ks], bh2);
                mma_bf16(sacc[nt], qh[ks], bl2);
                mma_bf16(sacc[nt], ql[ks], bh2);
            }
        }

        // + alibi + mask
#pragma unroll
        for (int nt = 0; nt < 8; nt++) {
            const int kc = nt*8 + c2;
            const float mk0 = Mk[kc]   ? -1e30f : 0.f;
            const float mk1 = Mk[kc+1] ? -1e30f : 0.f;
            sacc[nt][0] += ali0[nt].x + mk0;  sacc[nt][1] += ali0[nt].y + mk1;
            sacc[nt][2] += ali1[nt].x + mk0;  sacc[nt][3] += ali1[nt].y + mk1;
        }

        // online softmax
        float mx0 = -1e30f, mx1 = -1e30f;
#pragma unroll
        for (int nt = 0; nt < 8; nt++) {
            mx0 = fmaxf(mx0, fmaxf(sacc[nt][0], sacc[nt][1]));
            mx1 = fmaxf(mx1, fmaxf(sacc[nt][2], sacc[nt][3]));
        }
        mx0 = fmaxf(mx0, __shfl_xor_sync(0xffffffffu, mx0, 1));
        mx0 = fmaxf(mx0, __shfl_xor_sync(0xffffffffu, mx0, 2));
        mx1 = fmaxf(mx1, __shfl_xor_sync(0xffffffffu, mx1, 1));
        mx1 = fmaxf(mx1, __shfl_xor_sync(0xffffffffu, mx1, 2));

        const float mn0 = fmaxf(m0, mx0), mn1 = fmaxf(m1, mx1);
        const float cr0 = __expf(m0 - mn0), cr1 = __expf(m1 - mn1);
        float ls0 = 0.f, ls1 = 0.f;
#pragma unroll
        for (int nt = 0; nt < 8; nt++) {
            sacc[nt][0] = __expf(sacc[nt][0] - mn0);
            sacc[nt][1] = __expf(sacc[nt][1] - mn0);
            sacc[nt][2] = __expf(sacc[nt][2] - mn1);
            sacc[nt][3] = __expf(sacc[nt][3] - mn1);
            ls0 += sacc[nt][0] + sacc[nt][1];
            ls1 += sacc[nt][2] + sacc[nt][3];
        }
        ls0 += __shfl_xor_sync(0xffffffffu, ls0, 1);
        ls0 += __shfl_xor_sync(0xffffffffu, ls0, 2);
        ls1 += __shfl_xor_sync(0xffffffffu, ls1, 1);
        ls1 += __shfl_xor_sync(0xffffffffu, ls1, 2);
        l0 = l0*cr0 + ls0;  l1 = l1*cr1 + ls1;
        m0 = mn0;           m1 = mn1;

#pragma unroll
        for (int dt = 0; dt < 8; dt++) {
            o[dt][0] *= cr0; o[dt][1] *= cr0;
            o[dt][2] *= cr1; o[dt][3] *= cr1;
        }

        // O += P V
#pragma unroll
        for (int pk = 0; pk < 4; pk++) {
            uint32_t pa_h[4], pa_l[4];
            split_pack(sacc[2*pk][0],   sacc[2*pk][1],   pa_h[0], pa_l[0]);
            split_pack(sacc[2*pk][2],   sacc[2*pk][3],   pa_h[1], pa_l[1]);
            split_pack(sacc[2*pk+1][0], sacc[2*pk+1][1], pa_h[2], pa_l[2]);
            split_pack(sacc[2*pk+1][2], sacc[2*pk+1][3], pa_h[3], pa_l[3]);
            const int p = pk*8 + (lane & 3);
#pragma unroll
            for (int dt = 0; dt < 8; dt++) {
                const int dim = dt*8 + (lane >> 2);
                uint32_t vb_h[2] = { Vh[dim*PADA + p], Vh[dim*PADA + p + 4] };
                uint32_t vb_l[2] = { Vl[dim*PADA + p], Vl[dim*PADA + p + 4] };
                mma_bf16(o[dt], pa_h, vb_h);
                mma_bf16(o[dt], pa_h, vb_l);
                mma_bf16(o[dt], pa_l, vb_h);
            }
        }
        __syncthreads();
    }
#undef A_ISSUE

    // finalize: write hi/lo bf16 (feeds proj GEMM)
    const float inv0 = (l0 > 0.f) ? (1.f/l0) : 0.f;
    const float inv1 = (l1 > 0.f) ? (1.f/l1) : 0.f;
    const size_t i0 = ((size_t)b*Nseq + q0 + r0)*Cdim + h*HDd;
    const size_t i1 = i0 + (size_t)8*Cdim;
#pragma unroll
    for (int dt = 0; dt < 8; dt++) {
        uint32_t hh, ll;
        split_pack(o[dt][0]*inv0, o[dt][1]*inv0, hh, ll);
        *(uint32_t*)(g_aoh + i0 + dt*8 + c2) = hh;
        *(uint32_t*)(g_aol + i0 + dt*8 + c2) = ll;
        split_pack(o[dt][2]*inv1, o[dt][3]*inv1, hh, ll);
        *(uint32_t*)(g_aoh + i1 + dt*8 + c2) = hh;
        *(uint32_t*)(g_aol + i1 + dt*8 + c2) = ll;
    }
}

// ---------------------------------------------------------------------------
extern "C" void kernel_launch(void* const* d_in, const int* in_sizes, int n_in,
                              void* d_out, int out_size)
{
    const float* x      = (const float*)d_in[0];
    const int*   pmask  = (const int*)d_in[1];
    const float* alibi  = (const float*)d_in[2];
    const float* qkv_w  = (const float*)d_in[3];
    const float* proj_w = (const float*)d_in[4];
    const float* proj_b = (const float*)d_in[5];
    float*       out    = (float*)d_out;

    cudaFuncSetAttribute(gemm_mma<0>, cudaFuncAttributeMaxDynamicSharedMemorySize, GEMM_SMEM);
    cudaFuncSetAttribute(gemm_mma<1>, cudaFuncAttributeMaxDynamicSharedMemorySize, GEMM_SMEM);
    cudaFuncSetAttribute(attn_mma,    cudaFuncAttributeMaxDynamicSharedMemorySize, ATTN_SMEM);

    __nv_bfloat16 *xh, *xl, *qwh, *qwl, *pwh, *pwl, *aoh, *aol;
    cudaGetSymbolAddress((void**)&xh,  g_xh);  cudaGetSymbolAddress((void**)&xl,  g_xl);
    cudaGetSymbolAddress((void**)&qwh, g_qwh); cudaGetSymbolAddress((void**)&qwl, g_qwl);
    cudaGetSymbolAddress((void**)&pwh, g_pwh); cudaGetSymbolAddress((void**)&pwl, g_pwl);
    cudaGetSymbolAddress((void**)&aoh, g_aoh); cudaGetSymbolAddress((void**)&aol, g_aol);

    // 0) pre-split inputs/weights
    convert_split<<<(Mrows*Cdim/2 + 255)/256, 256>>>(x,      xh,  xl,  Mrows*Cdim/2);
    convert_split<<<(3*Cdim*Cdim/2 + 255)/256, 256>>>(qkv_w, qwh, qwl, 3*Cdim*Cdim/2);
    convert_split<<<(Cdim*Cdim/2 + 255)/256, 256>>>(proj_w,  pwh, pwl, Cdim*Cdim/2);

    // 1) QKV projection
    gemm_mma<0><<<dim3(24, 32), 256, GEMM_SMEM>>>(xh, xl, qwh, qwl, nullptr, nullptr);

    // 2) attention
    attn_mma<<<dim3(Nseq/64, Bq*Hh), 128, ATTN_SMEM>>>(alibi, pmask);

    // 3) output projection
    gemm_mma<1><<<dim3(8, 32), 256, GEMM_SMEM>>>(aoh, aol, pwh, pwl, proj_b, out);
}

// round 6
// speedup vs baseline: 1.6588x; 1.2670x over previous
#include <cuda_runtime.h>
#include <cuda_fp16.h>
#include <cstdint>

#define Bq    2
#define Nseq  2048
#define Cdim  1024
#define Hh    16
#define HDd   64
#define SCALE 0.125f
#define Mrows (Bq*Nseq)

// ---------------- device scratch ----------------
__device__ __half g_qa [(size_t)Bq*Hh*Nseq*HDd];   // Q fp16 (pre-scaled), [bh][n][d]
__device__ __half g_kh [(size_t)Bq*Hh*Nseq*HDd];   // K hi  [bh][key][dim]
__device__ __half g_kl [(size_t)Bq*Hh*Nseq*HDd];   // K lo
__device__ __half g_vth[(size_t)Bq*Hh*HDd*Nseq];   // V^T hi [bh][dim][key]
__device__ __half g_vtl[(size_t)Bq*Hh*HDd*Nseq];   // V^T lo
__device__ __half g_xa [(size_t)Mrows*Cdim];       // x fp16
__device__ __half g_qwh[(size_t)3*Cdim*Cdim];      // qkv_w hi
__device__ __half g_qwl[(size_t)3*Cdim*Cdim];      // qkv_w lo
__device__ __half g_pwh[(size_t)Cdim*Cdim];        // proj_w hi
__device__ __half g_pwl[(size_t)Cdim*Cdim];        // proj_w lo
__device__ __half g_ao [(size_t)Mrows*Cdim];       // attn out fp16

// ---------------- helpers ----------------
__device__ __forceinline__ void mma_f16(float* d, const uint32_t* a, const uint32_t* b)
{
    asm volatile(
        "mma.sync.aligned.m16n8k16.row.col.f32.f16.f16.f32 "
        "{%0,%1,%2,%3}, {%4,%5,%6,%7}, {%8,%9}, {%0,%1,%2,%3};"
        : "+f"(d[0]), "+f"(d[1]), "+f"(d[2]), "+f"(d[3])
        : "r"(a[0]), "r"(a[1]), "r"(a[2]), "r"(a[3]), "r"(b[0]), "r"(b[1]));
}

__device__ __forceinline__ uint32_t pack_h2(float x, float y)
{
    __half2 h = __floats2half2_rn(x, y);
    return *reinterpret_cast<uint32_t*>(&h);
}
__device__ __forceinline__ void split16(float x, float y, uint32_t& h, uint32_t& l)
{
    __half2 hv = __floats2half2_rn(x, y);
    float hx = __half2float(hv.x);
    float hy = __half2float(hv.y);
    __half2 lv = __floats2half2_rn(x - hx, y - hy);
    h = *reinterpret_cast<uint32_t*>(&hv);
    l = *reinterpret_cast<uint32_t*>(&lv);
}

__device__ __forceinline__ uint32_t smem_a(const void* p)
{
    return (uint32_t)__cvta_generic_to_shared(p);
}
__device__ __forceinline__ void cp16(uint32_t dst, const void* src)
{
    asm volatile("cp.async.cg.shared.global [%0], [%1], 16;\n" :: "r"(dst), "l"(src));
}
#define CP_COMMIT() asm volatile("cp.async.commit_group;\n")
template<int N> __device__ __forceinline__ void cp_wait()
{
    asm volatile("cp.async.wait_group %0;\n" :: "n"(N));
}

// ---------------- prep kernels ----------------
__global__ void conv_half(const float* __restrict__ src, __half* __restrict__ dst, int n2)
{
    int i = blockIdx.x * blockDim.x + threadIdx.x;
    if (i < n2) {
        float2 v = ((const float2*)src)[i];
        ((uint32_t*)dst)[i] = pack_h2(v.x, v.y);
    }
}
__global__ void conv_split(const float* __restrict__ src,
                           __half* __restrict__ h, __half* __restrict__ l, int n2)
{
    int i = blockIdx.x * blockDim.x + threadIdx.x;
    if (i < n2) {
        float2 v = ((const float2*)src)[i];
        uint32_t hh, ll;
        split16(v.x, v.y, hh, ll);
        ((uint32_t*)h)[i] = hh;
        ((uint32_t*)l)[i] = ll;
    }
}

// ---------------------------------------------------------------------------
// fp16 split GEMM, NT: out[m,j] = sum_k A[m,k]*W[j,k],  A fp16, W hi+lo.
// BM=BN=128, BK=32, 256 thr (2x4 warps), 3-stage cp.async, 1 barrier/iter.
// ---------------------------------------------------------------------------
#define PADK 20
#define G_A  (128*PADK)               // u32 per array
#define G_SU (3*G_A)                  // A, Wh, Wl
#define GEMM_SMEM (3*G_SU*4)          // 92160 B

template<int MODE>
__global__ void __launch_bounds__(256, 2) gemm_mma(
    const __half* __restrict__ A, const __half* __restrict__ W_h,
    const __half* __restrict__ W_l, const float* __restrict__ bias,
    float* __restrict__ out)
{
    extern __shared__ uint32_t sm[];

    const int tid  = threadIdx.x;
    const int lane = tid & 31;
    const int warp = tid >> 5;
    const int wm   = warp >> 2;
    const int wn   = warp & 3;
    const int rowBase = blockIdx.y * 128;
    const int colBase = blockIdx.x * 128;

    const int lr = tid >> 1, lh = tid & 1;
    const __half* pA  = A   + (size_t)(rowBase + lr) * Cdim + lh*16;
    const __half* pWh = W_h + (size_t)(colBase + lr) * Cdim + lh*16;
    const __half* pWl = W_l + (size_t)(colBase + lr) * Cdim + lh*16;
    const uint32_t dRow = (uint32_t)(lr*PADK + lh*8) * 4;
    const uint32_t sbase = smem_a(sm);

    float acc[4][4][4];
#pragma unroll
    for (int mt = 0; mt < 4; mt++)
#pragma unroll
        for (int nt = 0; nt < 4; nt++)
#pragma unroll
            for (int i = 0; i < 4; i++) acc[mt][nt][i] = 0.f;

#define G_ISSUE(s, k0)                                                  \
    do {                                                                \
        uint32_t b0 = sbase + (uint32_t)(s)*G_SU*4 + dRow;              \
        cp16(b0,              pA  + (k0)); cp16(b0 + 16,             pA  + (k0) + 8); \
        cp16(b0 + G_A*4,      pWh + (k0)); cp16(b0 + G_A*4 + 16,     pWh + (k0) + 8); \
        cp16(b0 + 2*G_A*4,    pWl + (k0)); cp16(b0 + 2*G_A*4 + 16,   pWl + (k0) + 8); \
    } while (0)

    G_ISSUE(0, 0);  CP_COMMIT();
    G_ISSUE(1, 32); CP_COMMIT();

    const int NIT = Cdim / 32;
    for (int it = 0; it < NIT; it++) {
        if (it + 1 < NIT) cp_wait<1>(); else cp_wait<0>();
        __syncthreads();
        if (it + 2 < NIT) { G_ISSUE((it+2)%3, (it+2)*32); CP_COMMIT(); }

        const int s = it % 3;
        const uint32_t* As = sm + s*G_SU;
        const uint32_t* Wh = As + G_A;
        const uint32_t* Wl = As + 2*G_A;

#pragma unroll
        for (int ks = 0; ks < 2; ks++) {
            uint32_t fa[4][4];
            const int p = ks*8 + (lane & 3);
#pragma unroll
            for (int mt = 0; mt < 4; mt++) {
                const int r = wm*64 + mt*16 + (lane >> 2);
                fa[mt][0] = As[r*PADK + p];
                fa[mt][1] = As[(r+8)*PADK + p];
                fa[mt][2] = As[r*PADK + p + 4];
                fa[mt][3] = As[(r+8)*PADK + p + 4];
            }
#pragma unroll
            for (int nt = 0; nt < 4; nt++) {
                const int n = wn*32 + nt*8 + (lane >> 2);
                uint32_t wh2[2] = { Wh[n*PADK + p], Wh[n*PADK + p + 4] };
                uint32_t wl2[2] = { Wl[n*PADK + p], Wl[n*PADK + p + 4] };
#pragma unroll
                for (int mt = 0; mt < 4; mt++) {
                    mma_f16(acc[mt][nt], fa[mt], wh2);
                    mma_f16(acc[mt][nt], fa[mt], wl2);
                }
            }
        }
    }
#undef G_ISSUE

    // epilogue
#pragma unroll
    for (int mt = 0; mt < 4; mt++) {
#pragma unroll
        for (int nt = 0; nt < 4; nt++) {
            const int r0 = rowBase + wm*64 + mt*16 + (lane >> 2);
            const int cc = colBase + wn*32 + nt*8 + 2*(lane & 3);
            if (MODE == 1) {
                float b0 = bias[cc], b1 = bias[cc+1];
                *(float2*)(out + (size_t)r0*Cdim + cc) =
                    make_float2(acc[mt][nt][0] + b0, acc[mt][nt][1] + b1);
                *(float2*)(out + (size_t)(r0+8)*Cdim + cc) =
                    make_float2(acc[mt][nt][2] + b0, acc[mt][nt][3] + b1);
            } else {
#pragma unroll
                for (int half_ = 0; half_ < 2; half_++) {
                    const int m  = r0 + half_*8;
                    const float v0 = acc[mt][nt][half_*2 + 0];
                    const float v1 = acc[mt][nt][half_*2 + 1];
                    const int bb = m >> 11, n = m & (Nseq-1);
                    const int which = cc >> 10, c = cc & (Cdim-1);
                    const int hh = c >> 6, d = c & 63;
                    const size_t bh = (size_t)bb*Hh + hh;
                    if (which == 0) {
                        const size_t idx = (bh*Nseq + n)*HDd + d;
                        *(uint32_t*)(g_qa + idx) = pack_h2(v0*SCALE, v1*SCALE);
                    } else if (which == 1) {
                        const size_t idx = (bh*Nseq + n)*HDd + d;
                        uint32_t h, l;
                        split16(v0, v1, h, l);
                        *(uint32_t*)(g_kh + idx) = h;
                        *(uint32_t*)(g_kl + idx) = l;
                    } else {
                        const size_t idx = (bh*HDd + d)*Nseq + n;  // transposed
                        __half2 hv = __floats2half2_rn(v0, v1);
                        float l0 = v0 - __half2float(hv.x);
                        float l1 = v1 - __half2float(hv.y);
                        __half2 lv = __floats2half2_rn(l0, l1);
                        g_vth[idx]        = hv.x;  g_vtl[idx]        = lv.x;
                        g_vth[idx + Nseq] = hv.y;  g_vtl[idx + Nseq] = lv.y;
                    }
                }
            }
        }
    }
}

// ---------------------------------------------------------------------------
// Flash attention, fp16 split (Q/P hi-only; K/V hi+lo), 3-stage cp.async.
// Grid: (N/128, B*H). Block: 256 (8 warps), warp w owns rows [w*16, w*16+16).
// ALiBi folded into accumulator init straight from gmem.
// ---------------------------------------------------------------------------
#define PADA 36
#define A_KV (64*PADA)                 // u32 per K/V array
#define A_SU (4*A_KV + 64)             // + mask
#define ATTN_SMEM (3*A_SU*4)           // 111360 B

__global__ void __launch_bounds__(256, 2) attn_mma(
    const float* __restrict__ alibi, const int* __restrict__ pmask)
{
    extern __shared__ uint32_t sm[];

    const int tid  = threadIdx.x;
    const int lane = tid & 31;
    const int warp = tid >> 5;
    const int bh   = blockIdx.y;
    const int b    = bh >> 4;
    const int h    = bh & 15;
    const int q0   = blockIdx.x * 128;

    const int r0 = warp*16 + (lane >> 2);   // local query row (also r0+8)
    const int c2 = 2*(lane & 3);

    // Q fragments (fp16, register-resident)
    uint32_t qa[4][4];
    {
        const __half* qb = g_qa + ((size_t)bh*Nseq + q0 + r0)*HDd;
#pragma unroll
        for (int ks = 0; ks < 4; ks++) {
            qa[ks][0] = *(const uint32_t*)(qb + ks*16 + c2);
            qa[ks][1] = *(const uint32_t*)(qb + 8*HDd + ks*16 + c2);
            qa[ks][2] = *(const uint32_t*)(qb + ks*16 + c2 + 8);
            qa[ks][3] = *(const uint32_t*)(qb + 8*HDd + ks*16 + c2 + 8);
        }
    }

    float o[8][4];
#pragma unroll
    for (int dt = 0; dt < 8; dt++)
#pragma unroll
        for (int i = 0; i < 4; i++) o[dt][i] = 0.f;
    float m0 = -1e30f, m1 = -1e30f, l0 = 0.f, l1 = 0.f;

    const __half* kh_g = g_kh  + (size_t)bh*Nseq*HDd;
    const __half* kl_g = g_kl  + (size_t)bh*Nseq*HDd;
    const __half* vh_g = g_vth + (size_t)bh*HDd*Nseq;
    const __half* vl_g = g_vtl + (size_t)bh*HDd*Nseq;
    const float*  ab   = alibi + ((size_t)bh*Nseq + q0)*Nseq;
    const int*    pm   = pmask + (size_t)b*Nseq;

    const uint32_t sbase = smem_a(sm);
    const int sr = tid >> 2;          // 0..63 staging row
    const int sq = tid & 3;           // quarter (8 u32 each)

#define A_ISSUE(s, k0)                                                        \
    do {                                                                      \
        const uint32_t st = sbase + (uint32_t)(s)*A_SU*4;                     \
        const uint32_t rb = (uint32_t)(sr*PADA + sq*8)*4;                     \
        const __half* k_h = kh_g + (size_t)((k0) + sr)*HDd + sq*16;           \
        const __half* k_l = kl_g + (size_t)((k0) + sr)*HDd + sq*16;           \
        const __half* v_h = vh_g + (size_t)sr*Nseq + (k0) + sq*16;            \
        const __half* v_l = vl_g + (size_t)sr*Nseq + (k0) + sq*16;            \
        cp16(st + rb,                 k_h);     cp16(st + rb + 16,                 k_h + 8); \
        cp16(st + A_KV*4   + rb,      k_l);     cp16(st + A_KV*4   + rb + 16,      k_l + 8); \
        cp16(st + 2*A_KV*4 + rb,      v_h);     cp16(st + 2*A_KV*4 + rb + 16,      v_h + 8); \
        cp16(st + 3*A_KV*4 + rb,      v_l);     cp16(st + 3*A_KV*4 + rb + 16,      v_l + 8); \
        if (tid < 16)                                                         \
            cp16(st + 4*A_KV*4 + tid*16, pm + (k0) + tid*4);                  \
    } while (0)

    A_ISSUE(0, 0);  CP_COMMIT();
    A_ISSUE(1, 64); CP_COMMIT();

    const int NIT = Nseq / 64;
    for (int it = 0; it < NIT; it++) {
        if (it + 1 < NIT) cp_wait<1>(); else cp_wait<0>();
        __syncthreads();
        if (it + 2 < NIT) { A_ISSUE((it+2)%3, (it+2)*64); CP_COMMIT(); }

        const int k0 = it * 64;
        const int s  = it % 3;
        const uint32_t* Kh = sm + s*A_SU;
        const uint32_t* Kl = Kh + A_KV;
        const uint32_t* Vh = Kh + 2*A_KV;
        const uint32_t* Vl = Kh + 3*A_KV;
        const int*      Mk = (const int*)(Kh + 4*A_KV);

        // init S with alibi + mask (LDGs overlap the mma chain)
        float sacc[8][4];
#pragma unroll
        for (int nt = 0; nt < 8; nt++) {
            const int kc = nt*8 + c2;
            const float mk0 = Mk[kc]   ? -1e30f : 0.f;
            const float mk1 = Mk[kc+1] ? -1e30f : 0.f;
            float2 a0 = *(const float2*)(ab + (size_t)r0*Nseq + k0 + kc);
            float2 a1 = *(const float2*)(ab + (size_t)(r0+8)*Nseq + k0 + kc);
            sacc[nt][0] = a0.x + mk0;  sacc[nt][1] = a0.y + mk1;
            sacc[nt][2] = a1.x + mk0;  sacc[nt][3] = a1.y + mk1;
        }

        // S += Q K^T
#pragma unroll
        for (int ks = 0; ks < 4; ks++) {
            const int p = ks*8 + (lane & 3);
#pragma unroll
            for (int nt = 0; nt < 8; nt++) {
                const int key = nt*8 + (lane >> 2);
                uint32_t kh2[2] = { Kh[key*PADA + p], Kh[key*PADA + p + 4] };
                uint32_t kl2[2] = { Kl[key*PADA + p], Kl[key*PADA + p + 4] };
                mma_f16(sacc[nt], qa[ks], kh2);
                mma_f16(sacc[nt], qa[ks], kl2);
            }
        }

        // online softmax (rows r0, r0+8)
        float mx0 = -1e30f, mx1 = -1e30f;
#pragma unroll
        for (int nt = 0; nt < 8; nt++) {
            mx0 = fmaxf(mx0, fmaxf(sacc[nt][0], sacc[nt][1]));
            mx1 = fmaxf(mx1, fmaxf(sacc[nt][2], sacc[nt][3]));
        }
        mx0 = fmaxf(mx0, __shfl_xor_sync(0xffffffffu, mx0, 1));
        mx0 = fmaxf(mx0, __shfl_xor_sync(0xffffffffu, mx0, 2));
        mx1 = fmaxf(mx1, __shfl_xor_sync(0xffffffffu, mx1, 1));
        mx1 = fmaxf(mx1, __shfl_xor_sync(0xffffffffu, mx1, 2));

        const float mn0 = fmaxf(m0, mx0), mn1 = fmaxf(m1, mx1);
        const float cr0 = __expf(m0 - mn0), cr1 = __expf(m1 - mn1);
        float ls0 = 0.f, ls1 = 0.f;
#pragma unroll
        for (int nt = 0; nt < 8; nt++) {
            sacc[nt][0] = __expf(sacc[nt][0] - mn0);
            sacc[nt][1] = __expf(sacc[nt][1] - mn0);
            sacc[nt][2] = __expf(sacc[nt][2] - mn1);
            sacc[nt][3] = __expf(sacc[nt][3] - mn1);
            ls0 += sacc[nt][0] + sacc[nt][1];
            ls1 += sacc[nt][2] + sacc[nt][3];
        }
        ls0 += __shfl_xor_sync(0xffffffffu, ls0, 1);
        ls0 += __shfl_xor_sync(0xffffffffu, ls0, 2);
        ls1 += __shfl_xor_sync(0xffffffffu, ls1, 1);
        ls1 += __shfl_xor_sync(0xffffffffu, ls1, 2);
        l0 = l0*cr0 + ls0;  l1 = l1*cr1 + ls1;
        m0 = mn0;           m1 = mn1;

#pragma unroll
        for (int dt = 0; dt < 8; dt++) {
            o[dt][0] *= cr0; o[dt][1] *= cr0;
            o[dt][2] *= cr1; o[dt][3] *= cr1;
        }

        // O += P V   (P rounded to fp16, hi only)
#pragma unroll
        for (int pk = 0; pk < 4; pk++) {
            uint32_t pa[4];
            pa[0] = pack_h2(sacc[2*pk][0],   sacc[2*pk][1]);
            pa[1] = pack_h2(sacc[2*pk][2],   sacc[2*pk][3]);
            pa[2] = pack_h2(sacc[2*pk+1][0], sacc[2*pk+1][1]);
            pa[3] = pack_h2(sacc[2*pk+1][2], sacc[2*pk+1][3]);
            const int p = pk*8 + (lane & 3);
#pragma unroll
            for (int dt = 0; dt < 8; dt++) {
                const int dim = dt*8 + (lane >> 2);
                uint32_t vh2[2] = { Vh[dim*PADA + p], Vh[dim*PADA + p + 4] };
                uint32_t vl2[2] = { Vl[dim*PADA + p], Vl[dim*PADA + p + 4] };
                mma_f16(o[dt], pa, vh2);
                mma_f16(o[dt], pa, vl2);
            }
        }
    }
#undef A_ISSUE

    // finalize: fp16 output (feeds proj GEMM A-side)
    const float inv0 = (l0 > 0.f) ? (1.f/l0) : 0.f;
    const float inv1 = (l1 > 0.f) ? (1.f/l1) : 0.f;
    const size_t i0 = ((size_t)b*Nseq + q0 + r0)*Cdim + h*HDd;
    const size_t i1 = i0 + (size_t)8*Cdim;
#pragma unroll
    for (int dt = 0; dt < 8; dt++) {
        *(uint32_t*)(g_ao + i0 + dt*8 + c2) = pack_h2(o[dt][0]*inv0, o[dt][1]*inv0);
        *(uint32_t*)(g_ao + i1 + dt*8 + c2) = pack_h2(o[dt][2]*inv1, o[dt][3]*inv1);
    }
}

// ---------------------------------------------------------------------------
extern "C" void kernel_launch(void* const* d_in, const int* in_sizes, int n_in,
                              void* d_out, int out_size)
{
    const float* x      = (const float*)d_in[0];
    const int*   pmask  = (const int*)d_in[1];
    const float* alibi  = (const float*)d_in[2];
    const float* qkv_w  = (const float*)d_in[3];
    const float* proj_w = (const float*)d_in[4];
    const float* proj_b = (const float*)d_in[5];
    float*       out    = (float*)d_out;

    cudaFuncSetAttribute(gemm_mma<0>, cudaFuncAttributeMaxDynamicSharedMemorySize, GEMM_SMEM);
    cudaFuncSetAttribute(gemm_mma<1>, cudaFuncAttributeMaxDynamicSharedMemorySize, GEMM_SMEM);
    cudaFuncSetAttribute(attn_mma,    cudaFuncAttributeMaxDynamicSharedMemorySize, ATTN_SMEM);

    __half *xa, *qwh, *qwl, *pwh, *pwl, *ao;
    cudaGetSymbolAddress((void**)&xa,  g_xa);
    cudaGetSymbolAddress((void**)&qwh, g_qwh); cudaGetSymbolAddress((void**)&qwl, g_qwl);
    cudaGetSymbolAddress((void**)&pwh, g_pwh); cudaGetSymbolAddress((void**)&pwl, g_pwl);
    cudaGetSymbolAddress((void**)&ao,  g_ao);

    // 0) pre-convert
    conv_half <<<(Mrows*Cdim/2 + 255)/256, 256>>>(x, xa, Mrows*Cdim/2);
    conv_split<<<(3*Cdim*Cdim/2 + 255)/256, 256>>>(qkv_w, qwh, qwl, 3*Cdim*Cdim/2);
    conv_split<<<(Cdim*Cdim/2 + 255)/256, 256>>>(proj_w,  pwh, pwl, Cdim*Cdim/2);

    // 1) QKV projection
    gemm_mma<0><<<dim3(24, 32), 256, GEMM_SMEM>>>(xa, qwh, qwl, nullptr, nullptr);

    // 2) attention
    attn_mma<<<dim3(Nseq/128, Bq*Hh), 256, ATTN_SMEM>>>(alibi, pmask);

    // 3) output projection
    gemm_mma<1><<<dim3(8, 32), 256, GEMM_SMEM>>>(ao, pwh, pwl, proj_b, out);
}

// round 7
// speedup vs baseline: 1.9088x; 1.1507x over previous
#include <cuda_runtime.h>
#include <cuda_fp16.h>
#include <cstdint>

#define Bq    2
#define Nseq  2048
#define Cdim  1024
#define Hh    16
#define HDd   64
#define SCALE 0.125f
#define Mrows (Bq*Nseq)

// ---------------- device scratch ----------------
__device__ __half g_qa [(size_t)Bq*Hh*Nseq*HDd];   // Q fp16 (pre-scaled), [bh][n][d]
__device__ __half g_kh [(size_t)Bq*Hh*Nseq*HDd];   // K hi  [bh][key][dim]
__device__ __half g_kl [(size_t)Bq*Hh*Nseq*HDd];   // K lo
__device__ __half g_vth[(size_t)Bq*Hh*HDd*Nseq];   // V^T hi [bh][dim][key]
__device__ __half g_vtl[(size_t)Bq*Hh*HDd*Nseq];   // V^T lo
__device__ __half g_xa [(size_t)Mrows*Cdim];       // x fp16
__device__ __half g_qwh[(size_t)3*Cdim*Cdim];      // qkv_w hi
__device__ __half g_qwl[(size_t)3*Cdim*Cdim];      // qkv_w lo
__device__ __half g_pwh[(size_t)Cdim*Cdim];        // proj_w hi
__device__ __half g_pwl[(size_t)Cdim*Cdim];        // proj_w lo
__device__ __half g_ao [(size_t)Mrows*Cdim];       // attn out fp16

// ---------------- helpers ----------------
__device__ __forceinline__ void mma_f16(float* d, const uint32_t* a, const uint32_t* b)
{
    asm volatile(
        "mma.sync.aligned.m16n8k16.row.col.f32.f16.f16.f32 "
        "{%0,%1,%2,%3}, {%4,%5,%6,%7}, {%8,%9}, {%0,%1,%2,%3};"
        : "+f"(d[0]), "+f"(d[1]), "+f"(d[2]), "+f"(d[3])
        : "r"(a[0]), "r"(a[1]), "r"(a[2]), "r"(a[3]), "r"(b[0]), "r"(b[1]));
}

__device__ __forceinline__ void ldsm_x4(uint32_t* r, uint32_t saddr)
{
    asm volatile(
        "ldmatrix.sync.aligned.m8n8.x4.shared.b16 {%0,%1,%2,%3}, [%4];"
        : "=r"(r[0]), "=r"(r[1]), "=r"(r[2]), "=r"(r[3]) : "r"(saddr));
}

__device__ __forceinline__ uint32_t pack_h2(float x, float y)
{
    __half2 h = __floats2half2_rn(x, y);
    return *reinterpret_cast<uint32_t*>(&h);
}
__device__ __forceinline__ void split16(float x, float y, uint32_t& h, uint32_t& l)
{
    __half2 hv = __floats2half2_rn(x, y);
    float hx = __half2float(hv.x);
    float hy = __half2float(hv.y);
    __half2 lv = __floats2half2_rn(x - hx, y - hy);
    h = *reinterpret_cast<uint32_t*>(&hv);
    l = *reinterpret_cast<uint32_t*>(&lv);
}

__device__ __forceinline__ uint32_t smem_a(const void* p)
{
    return (uint32_t)__cvta_generic_to_shared(p);
}
__device__ __forceinline__ void cp16(uint32_t dst, const void* src)
{
    asm volatile("cp.async.cg.shared.global [%0], [%1], 16;\n" :: "r"(dst), "l"(src));
}
#define CP_COMMIT() asm volatile("cp.async.commit_group;\n")
template<int N> __device__ __forceinline__ void cp_wait()
{
    asm volatile("cp.async.wait_group %0;\n" :: "n"(N));
}

// ---------------- prep kernels ----------------
__global__ void conv_half(const float* __restrict__ src, __half* __restrict__ dst, int n2)
{
    int i = blockIdx.x * blockDim.x + threadIdx.x;
    if (i < n2) {
        float2 v = ((const float2*)src)[i];
        ((uint32_t*)dst)[i] = pack_h2(v.x, v.y);
    }
}
__global__ void conv_split(const float* __restrict__ src,
                           __half* __restrict__ h, __half* __restrict__ l, int n2)
{
    int i = blockIdx.x * blockDim.x + threadIdx.x;
    if (i < n2) {
        float2 v = ((const float2*)src)[i];
        uint32_t hh, ll;
        split16(v.x, v.y, hh, ll);
        ((uint32_t*)h)[i] = hh;
        ((uint32_t*)l)[i] = ll;
    }
}

// ---------------------------------------------------------------------------
// fp16 split GEMM, NT: out[m,j] = sum_k A[m,k]*W[j,k],  A fp16, W hi+lo.
// BM=BN=128, BK=32, 256 thr (2x4 warps), 3-stage cp.async, ldmatrix frags.
// ---------------------------------------------------------------------------
#define PADK 20
#define G_A  (128*PADK)               // u32 per array
#define G_SU (3*G_A)                  // A, Wh, Wl
#define GEMM_SMEM (3*G_SU*4)          // 92160 B

template<int MODE>
__global__ void __launch_bounds__(256, 2) gemm_mma(
    const __half* __restrict__ A, const __half* __restrict__ W_h,
    const __half* __restrict__ W_l, const float* __restrict__ bias,
    float* __restrict__ out)
{
    extern __shared__ uint32_t sm[];

    const int tid  = threadIdx.x;
    const int lane = tid & 31;
    const int warp = tid >> 5;
    const int wm   = warp >> 2;
    const int wn   = warp & 3;
    const int rowBase = blockIdx.y * 128;
    const int colBase = blockIdx.x * 128;

    // ldmatrix per-lane addressing
    const int lrow8 = lane & 7;
    const int lsel  = lane >> 3;                 // 0..3
    const int a_row = (lsel & 1)*8 + lrow8;      // A: mat0 m0-7/k0-7, mat1 m8-15/k0-7, mat2 m0-7/k8-15, mat3 m8-15/k8-15
    const int a_col = (lsel >> 1)*4;
    const int b_row = (lsel >> 1)*8 + lrow8;     // B: mat0 n0-7/k0-7, mat1 n0-7/k8-15, mat2 n8-15/k0-7, mat3 n8-15/k8-15
    const int b_col = (lsel & 1)*4;

    const int lr = tid >> 1, lh = tid & 1;
    const __half* pA  = A   + (size_t)(rowBase + lr) * Cdim + lh*16;
    const __half* pWh = W_h + (size_t)(colBase + lr) * Cdim + lh*16;
    const __half* pWl = W_l + (size_t)(colBase + lr) * Cdim + lh*16;
    const uint32_t dRow = (uint32_t)(lr*PADK + lh*8) * 4;
    const uint32_t sbase = smem_a(sm);

    float acc[4][4][4];
#pragma unroll
    for (int mt = 0; mt < 4; mt++)
#pragma unroll
        for (int nt = 0; nt < 4; nt++)
#pragma unroll
            for (int i = 0; i < 4; i++) acc[mt][nt][i] = 0.f;

#define G_ISSUE(s, k0)                                                  \
    do {                                                                \
        uint32_t b0 = sbase + (uint32_t)(s)*G_SU*4 + dRow;              \
        cp16(b0,              pA  + (k0)); cp16(b0 + 16,             pA  + (k0) + 8); \
        cp16(b0 + G_A*4,      pWh + (k0)); cp16(b0 + G_A*4 + 16,     pWh + (k0) + 8); \
        cp16(b0 + 2*G_A*4,    pWl + (k0)); cp16(b0 + 2*G_A*4 + 16,   pWl + (k0) + 8); \
    } while (0)

    G_ISSUE(0, 0);  CP_COMMIT();
    G_ISSUE(1, 32); CP_COMMIT();

    const int NIT = Cdim / 32;
    for (int it = 0; it < NIT; it++) {
        if (it + 1 < NIT) cp_wait<1>(); else cp_wait<0>();
        __syncthreads();
        if (it + 2 < NIT) { G_ISSUE((it+2)%3, (it+2)*32); CP_COMMIT(); }

        const int s = it % 3;
        const uint32_t Abyte  = sbase + (uint32_t)(s*G_SU)*4;
        const uint32_t Whbyte = Abyte + G_A*4;
        const uint32_t Wlbyte = Abyte + 2*G_A*4;

#pragma unroll
        for (int ks = 0; ks < 2; ks++) {
            uint32_t fa[4][4];
#pragma unroll
            for (int mt = 0; mt < 4; mt++)
                ldsm_x4(fa[mt], Abyte + (uint32_t)(((wm*64 + mt*16 + a_row)*PADK) + ks*8 + a_col)*4);
#pragma unroll
            for (int pr = 0; pr < 2; pr++) {
                uint32_t wh4[4], wl4[4];
                const uint32_t wofs = (uint32_t)(((wn*32 + pr*16 + b_row)*PADK) + ks*8 + b_col)*4;
                ldsm_x4(wh4, Whbyte + wofs);
                ldsm_x4(wl4, Wlbyte + wofs);
#pragma unroll
                for (int mt = 0; mt < 4; mt++) {
                    mma_f16(acc[mt][2*pr],   fa[mt], wh4);
                    mma_f16(acc[mt][2*pr],   fa[mt], wl4);
                    mma_f16(acc[mt][2*pr+1], fa[mt], wh4 + 2);
                    mma_f16(acc[mt][2*pr+1], fa[mt], wl4 + 2);
                }
            }
        }
    }
#undef G_ISSUE

    // epilogue
#pragma unroll
    for (int mt = 0; mt < 4; mt++) {
#pragma unroll
        for (int nt = 0; nt < 4; nt++) {
            const int r0 = rowBase + wm*64 + mt*16 + (lane >> 2);
            const int cc = colBase + wn*32 + nt*8 + 2*(lane & 3);
            if (MODE == 1) {
                float b0 = bias[cc], b1 = bias[cc+1];
                *(float2*)(out + (size_t)r0*Cdim + cc) =
                    make_float2(acc[mt][nt][0] + b0, acc[mt][nt][1] + b1);
                *(float2*)(out + (size_t)(r0+8)*Cdim + cc) =
                    make_float2(acc[mt][nt][2] + b0, acc[mt][nt][3] + b1);
            } else {
#pragma unroll
                for (int half_ = 0; half_ < 2; half_++) {
                    const int m  = r0 + half_*8;
                    const float v0 = acc[mt][nt][half_*2 + 0];
                    const float v1 = acc[mt][nt][half_*2 + 1];
                    const int bb = m >> 11, n = m & (Nseq-1);
                    const int which = cc >> 10, c = cc & (Cdim-1);
                    const int hh = c >> 6, d = c & 63;
                    const size_t bh = (size_t)bb*Hh + hh;
                    if (which == 0) {
                        const size_t idx = (bh*Nseq + n)*HDd + d;
                        *(uint32_t*)(g_qa + idx) = pack_h2(v0*SCALE, v1*SCALE);
                    } else if (which == 1) {
                        const size_t idx = (bh*Nseq + n)*HDd + d;
                        uint32_t h, l;
                        split16(v0, v1, h, l);
                        *(uint32_t*)(g_kh + idx) = h;
                        *(uint32_t*)(g_kl + idx) = l;
                    } else {
                        const size_t idx = (bh*HDd + d)*Nseq + n;  // transposed
                        __half2 hv = __floats2half2_rn(v0, v1);
                        float l0 = v0 - __half2float(hv.x);
                        float l1 = v1 - __half2float(hv.y);
                        __half2 lv = __floats2half2_rn(l0, l1);
                        g_vth[idx]        = hv.x;  g_vtl[idx]        = lv.x;
                        g_vth[idx + Nseq] = hv.y;  g_vtl[idx + Nseq] = lv.y;
                    }
                }
            }
        }
    }
}

// ---------------------------------------------------------------------------
// Flash attention, fp16 split (Q/P hi-only; K/V hi+lo), 3-stage cp.async,
// ldmatrix fragments, ALiBi prefetched into registers (added AFTER the
// S-mma chain so DRAM latency hides under tensor work).
// Grid: (N/128, B*H). Block: 256 (8 warps).
// ---------------------------------------------------------------------------
#define PADA 36
#define A_KV (64*PADA)                 // u32 per K/V array
#define A_SU (4*A_KV + 64)             // + mask
#define ATTN_SMEM (3*A_SU*4)           // 111360 B

__global__ void __launch_bounds__(256, 2) attn_mma(
    const float* __restrict__ alibi, const int* __restrict__ pmask)
{
    extern __shared__ uint32_t sm[];

    const int tid  = threadIdx.x;
    const int lane = tid & 31;
    const int warp = tid >> 5;
    const int bh   = blockIdx.y;
    const int b    = bh >> 4;
    const int h    = bh & 15;
    const int q0   = blockIdx.x * 128;

    const int r0 = warp*16 + (lane >> 2);
    const int c2 = 2*(lane & 3);

    const int lrow8 = lane & 7;
    const int lsel  = lane >> 3;
    const int b_row = (lsel >> 1)*8 + lrow8;
    const int b_col = (lsel & 1)*4;

    // Q fragments (fp16, register-resident)
    uint32_t qa[4][4];
    {
        const __half* qb = g_qa + ((size_t)bh*Nseq + q0 + r0)*HDd;
#pragma unroll
        for (int ks = 0; ks < 4; ks++) {
            qa[ks][0] = *(const uint32_t*)(qb + ks*16 + c2);
            qa[ks][1] = *(const uint32_t*)(qb + 8*HDd + ks*16 + c2);
            qa[ks][2] = *(const uint32_t*)(qb + ks*16 + c2 + 8);
            qa[ks][3] = *(const uint32_t*)(qb + 8*HDd + ks*16 + c2 + 8);
        }
    }

    float o[8][4];
#pragma unroll
    for (int dt = 0; dt < 8; dt++)
#pragma unroll
        for (int i = 0; i < 4; i++) o[dt][i] = 0.f;
    float m0 = -1e30f, m1 = -1e30f, l0 = 0.f, l1 = 0.f;

    const __half* kh_g = g_kh  + (size_t)bh*Nseq*HDd;
    const __half* kl_g = g_kl  + (size_t)bh*Nseq*HDd;
    const __half* vh_g = g_vth + (size_t)bh*HDd*Nseq;
    const __half* vl_g = g_vtl + (size_t)bh*HDd*Nseq;
    const float*  ab   = alibi + ((size_t)bh*Nseq + q0)*Nseq;
    const int*    pm   = pmask + (size_t)b*Nseq;

    const uint32_t sbase = smem_a(sm);
    const int sr = tid >> 2;
    const int sq = tid & 3;

#define A_ISSUE(s, k0)                                                        \
    do {                                                                      \
        const uint32_t st = sbase + (uint32_t)(s)*A_SU*4;                     \
        const uint32_t rb = (uint32_t)(sr*PADA + sq*8)*4;                     \
        const __half* k_h = kh_g + (size_t)((k0) + sr)*HDd + sq*16;           \
        const __half* k_l = kl_g + (size_t)((k0) + sr)*HDd + sq*16;           \
        const __half* v_h = vh_g + (size_t)sr*Nseq + (k0) + sq*16;            \
        const __half* v_l = vl_g + (size_t)sr*Nseq + (k0) + sq*16;            \
        cp16(st + rb,                 k_h);     cp16(st + rb + 16,                 k_h + 8); \
        cp16(st + A_KV*4   + rb,      k_l);     cp16(st + A_KV*4   + rb + 16,      k_l + 8); \
        cp16(st + 2*A_KV*4 + rb,      v_h);     cp16(st + 2*A_KV*4 + rb + 16,      v_h + 8); \
        cp16(st + 3*A_KV*4 + rb,      v_l);     cp16(st + 3*A_KV*4 + rb + 16,      v_l + 8); \
        if (tid < 16)                                                         \
            cp16(st + 4*A_KV*4 + tid*16, pm + (k0) + tid*4);                  \
    } while (0)

    A_ISSUE(0, 0);  CP_COMMIT();
    A_ISSUE(1, 64); CP_COMMIT();

    const int NIT = Nseq / 64;
    for (int it = 0; it < NIT; it++) {
        if (it + 1 < NIT) cp_wait<1>(); else cp_wait<0>();
        __syncthreads();
        if (it + 2 < NIT) { A_ISSUE((it+2)%3, (it+2)*64); CP_COMMIT(); }

        const int k0 = it * 64;
        const int s  = it % 3;
        const uint32_t Khb = sbase + (uint32_t)(s*A_SU)*4;
        const uint32_t Klb = Khb + A_KV*4;
        const uint32_t Vhb = Khb + 2*A_KV*4;
        const uint32_t Vlb = Khb + 3*A_KV*4;
        const int* Mk = (const int*)(sm + s*A_SU + 4*A_KV);

        // Prefetch ALiBi into registers NOW; consumed only after the S-mma
        // chain, so the DRAM latency hides under tensor work.
        float2 ali0[8], ali1[8];
#pragma unroll
        for (int nt = 0; nt < 8; nt++) {
            const int kc = nt*8 + c2;
            ali0[nt] = *(const float2*)(ab + (size_t)r0*Nseq + k0 + kc);
            ali1[nt] = *(const float2*)(ab + (size_t)(r0+8)*Nseq + k0 + kc);
        }

        // S = Q K^T (zero-init, no memory dependency)
        float sacc[8][4];
#pragma unroll
        for (int nt = 0; nt < 8; nt++)
#pragma unroll
            for (int i = 0; i < 4; i++) sacc[nt][i] = 0.f;
#pragma unroll
        for (int ks = 0; ks < 4; ks++) {
#pragma unroll
            for (int pr = 0; pr < 4; pr++) {
                uint32_t kh4[4], kl4[4];
                const uint32_t kofs = (uint32_t)(((pr*16 + b_row)*PADA) + ks*8 + b_col)*4;
                ldsm_x4(kh4, Khb + kofs);
                ldsm_x4(kl4, Klb + kofs);
                mma_f16(sacc[2*pr],   qa[ks], kh4);
                mma_f16(sacc[2*pr],   qa[ks], kl4);
                mma_f16(sacc[2*pr+1], qa[ks], kh4 + 2);
                mma_f16(sacc[2*pr+1], qa[ks], kl4 + 2);
            }
        }

        // + alibi + mask (registers landed during the chain)
#pragma unroll
        for (int nt = 0; nt < 8; nt++) {
            const int kc = nt*8 + c2;
            const float mk0 = Mk[kc]   ? -1e30f : 0.f;
            const float mk1 = Mk[kc+1] ? -1e30f : 0.f;
            sacc[nt][0] += ali0[nt].x + mk0;  sacc[nt][1] += ali0[nt].y + mk1;
            sacc[nt][2] += ali1[nt].x + mk0;  sacc[nt][3] += ali1[nt].y + mk1;
        }

        // online softmax (rows r0, r0+8)
        float mx0 = -1e30f, mx1 = -1e30f;
#pragma unroll
        for (int nt = 0; nt < 8; nt++) {
            mx0 = fmaxf(mx0, fmaxf(sacc[nt][0], sacc[nt][1]));
            mx1 = fmaxf(mx1, fmaxf(sacc[nt][2], sacc[nt][3]));
        }
        mx0 = fmaxf(mx0, __shfl_xor_sync(0xffffffffu, mx0, 1));
        mx0 = fmaxf(mx0, __shfl_xor_sync(0xffffffffu, mx0, 2));
        mx1 = fmaxf(mx1, __shfl_xor_sync(0xffffffffu, mx1, 1));
        mx1 = fmaxf(mx1, __shfl_xor_sync(0xffffffffu, mx1, 2));

        const float mn0 = fmaxf(m0, mx0), mn1 = fmaxf(m1, mx1);
        const float cr0 = __expf(m0 - mn0), cr1 = __expf(m1 - mn1);
        float ls0 = 0.f, ls1 = 0.f;
#pragma unroll
        for (int nt = 0; nt < 8; nt++) {
            sacc[nt][0] = __expf(sacc[nt][0] - mn0);
            sacc[nt][1] = __expf(sacc[nt][1] - mn0);
            sacc[nt][2] = __expf(sacc[nt][2] - mn1);
            sacc[nt][3] = __expf(sacc[nt][3] - mn1);
            ls0 += sacc[nt][0] + sacc[nt][1];
            ls1 += sacc[nt][2] + sacc[nt][3];
        }
        ls0 += __shfl_xor_sync(0xffffffffu, ls0, 1);
        ls0 += __shfl_xor_sync(0xffffffffu, ls0, 2);
        ls1 += __shfl_xor_sync(0xffffffffu, ls1, 1);
        ls1 += __shfl_xor_sync(0xffffffffu, ls1, 2);
        l0 = l0*cr0 + ls0;  l1 = l1*cr1 + ls1;
        m0 = mn0;           m1 = mn1;

#pragma unroll
        for (int dt = 0; dt < 8; dt++) {
            o[dt][0] *= cr0; o[dt][1] *= cr0;
            o[dt][2] *= cr1; o[dt][3] *= cr1;
        }

        // O += P V   (P rounded to fp16, hi only)
#pragma unroll
        for (int pk = 0; pk < 4; pk++) {
            uint32_t pa[4];
            pa[0] = pack_h2(sacc[2*pk][0],   sacc[2*pk][1]);
            pa[1] = pack_h2(sacc[2*pk][2],   sacc[2*pk][3]);
            pa[2] = pack_h2(sacc[2*pk+1][0], sacc[2*pk+1][1]);
            pa[3] = pack_h2(sacc[2*pk+1][2], sacc[2*pk+1][3]);
#pragma unroll
            for (int pr = 0; pr < 4; pr++) {
                uint32_t vh4[4], vl4[4];
                const uint32_t vofs = (uint32_t)(((pr*16 + b_row)*PADA) + pk*8 + b_col)*4;
                ldsm_x4(vh4, Vhb + vofs);
                ldsm_x4(vl4, Vlb + vofs);
                mma_f16(o[2*pr],   pa, vh4);
                mma_f16(o[2*pr],   pa, vl4);
                mma_f16(o[2*pr+1], pa, vh4 + 2);
                mma_f16(o[2*pr+1], pa, vl4 + 2);
            }
        }
    }
#undef A_ISSUE

    // finalize: fp16 output (feeds proj GEMM A-side)
    const float inv0 = (l0 > 0.f) ? (1.f/l0) : 0.f;
    const float inv1 = (l1 > 0.f) ? (1.f/l1) : 0.f;
    const size_t i0 = ((size_t)b*Nseq + q0 + r0)*Cdim + h*HDd;
    const size_t i1 = i0 + (size_t)8*Cdim;
#pragma unroll
    for (int dt = 0; dt < 8; dt++) {
        *(uint32_t*)(g_ao + i0 + dt*8 + c2) = pack_h2(o[dt][0]*inv0, o[dt][1]*inv0);
        *(uint32_t*)(g_ao + i1 + dt*8 + c2) = pack_h2(o[dt][2]*inv1, o[dt][3]*inv1);
    }
}

// ---------------------------------------------------------------------------
extern "C" void kernel_launch(void* const* d_in, const int* in_sizes, int n_in,
                              void* d_out, int out_size)
{
    const float* x      = (const float*)d_in[0];
    const int*   pmask  = (const int*)d_in[1];
    const float* alibi  = (const float*)d_in[2];
    const float* qkv_w  = (const float*)d_in[3];
    const float* proj_w = (const float*)d_in[4];
    const float* proj_b = (const float*)d_in[5];
    float*       out    = (float*)d_out;

    cudaFuncSetAttribute(gemm_mma<0>, cudaFuncAttributeMaxDynamicSharedMemorySize, GEMM_SMEM);
    cudaFuncSetAttribute(gemm_mma<1>, cudaFuncAttributeMaxDynamicSharedMemorySize, GEMM_SMEM);
    cudaFuncSetAttribute(attn_mma,    cudaFuncAttributeMaxDynamicSharedMemorySize, ATTN_SMEM);

    __half *xa, *qwh, *qwl, *pwh, *pwl, *ao;
    cudaGetSymbolAddress((void**)&xa,  g_xa);
    cudaGetSymbolAddress((void**)&qwh, g_qwh); cudaGetSymbolAddress((void**)&qwl, g_qwl);
    cudaGetSymbolAddress((void**)&pwh, g_pwh); cudaGetSymbolAddress((void**)&pwl, g_pwl);
    cudaGetSymbolAddress((void**)&ao,  g_ao);

    // 0) pre-convert
    conv_half <<<(Mrows*Cdim/2 + 255)/256, 256>>>(x, xa, Mrows*Cdim/2);
    conv_split<<<(3*Cdim*Cdim/2 + 255)/256, 256>>>(qkv_w, qwh, qwl, 3*Cdim*Cdim/2);
    conv_split<<<(Cdim*Cdim/2 + 255)/256, 256>>>(proj_w,  pwh, pwl, Cdim*Cdim/2);

    // 1) QKV projection
    gemm_mma<0><<<dim3(24, 32), 256, GEMM_SMEM>>>(xa, qwh, qwl, nullptr, nullptr);

    // 2) attention
    attn_mma<<<dim3(Nseq/128, Bq*Hh), 256, ATTN_SMEM>>>(alibi, pmask);

    // 3) output projection
    gemm_mma<1><<<dim3(8, 32), 256, GEMM_SMEM>>>(ao, pwh, pwl, proj_b, out);
}

// round 8
// speedup vs baseline: 2.3589x; 1.2358x over previous
#include <cuda_runtime.h>
#include <cuda_fp16.h>
#include <cstdint>

#define Bq    2
#define Nseq  2048
#define Cdim  1024
#define Hh    16
#define HDd   64
#define SCALE 0.125f
#define Mrows (Bq*Nseq)

// ---------------- device scratch ----------------
__device__ __half g_qa [(size_t)Bq*Hh*Nseq*HDd];   // Q fp16 (pre-scaled), [bh][n][d]
__device__ __half g_kh [(size_t)Bq*Hh*Nseq*HDd];   // K fp16 [bh][key][dim]
__device__ __half g_vth[(size_t)Bq*Hh*HDd*Nseq];   // V^T fp16 [bh][dim][key]
__device__ __half g_xa [(size_t)Mrows*Cdim];       // x fp16
__device__ __half g_qwh[(size_t)3*Cdim*Cdim];      // qkv_w hi
__device__ __half g_qwl[(size_t)3*Cdim*Cdim];      // qkv_w lo
__device__ __half g_pwh[(size_t)Cdim*Cdim];        // proj_w hi
__device__ __half g_pwl[(size_t)Cdim*Cdim];        // proj_w lo
__device__ __half g_ao [(size_t)Mrows*Cdim];       // attn out fp16

// ---------------- helpers ----------------
__device__ __forceinline__ void mma_f16(float* d, const uint32_t* a, const uint32_t* b)
{
    asm volatile(
        "mma.sync.aligned.m16n8k16.row.col.f32.f16.f16.f32 "
        "{%0,%1,%2,%3}, {%4,%5,%6,%7}, {%8,%9}, {%0,%1,%2,%3};"
        : "+f"(d[0]), "+f"(d[1]), "+f"(d[2]), "+f"(d[3])
        : "r"(a[0]), "r"(a[1]), "r"(a[2]), "r"(a[3]), "r"(b[0]), "r"(b[1]));
}

__device__ __forceinline__ void ldsm_x4(uint32_t* r, uint32_t saddr)
{
    asm volatile(
        "ldmatrix.sync.aligned.m8n8.x4.shared.b16 {%0,%1,%2,%3}, [%4];"
        : "=r"(r[0]), "=r"(r[1]), "=r"(r[2]), "=r"(r[3]) : "r"(saddr));
}

__device__ __forceinline__ uint32_t pack_h2(float x, float y)
{
    __half2 h = __floats2half2_rn(x, y);
    return *reinterpret_cast<uint32_t*>(&h);
}
__device__ __forceinline__ void split16(float x, float y, uint32_t& h, uint32_t& l)
{
    __half2 hv = __floats2half2_rn(x, y);
    float hx = __half2float(hv.x);
    float hy = __half2float(hv.y);
    __half2 lv = __floats2half2_rn(x - hx, y - hy);
    h = *reinterpret_cast<uint32_t*>(&hv);
    l = *reinterpret_cast<uint32_t*>(&lv);
}

__device__ __forceinline__ uint32_t smem_a(const void* p)
{
    return (uint32_t)__cvta_generic_to_shared(p);
}
__device__ __forceinline__ void cp16(uint32_t dst, const void* src)
{
    asm volatile("cp.async.cg.shared.global [%0], [%1], 16;\n" :: "r"(dst), "l"(src));
}
#define CP_COMMIT() asm volatile("cp.async.commit_group;\n")
template<int N> __device__ __forceinline__ void cp_wait()
{
    asm volatile("cp.async.wait_group %0;\n" :: "n"(N));
}

// ---------------- prep kernels ----------------
__global__ void conv_half(const float* __restrict__ src, __half* __restrict__ dst, int n2)
{
    int i = blockIdx.x * blockDim.x + threadIdx.x;
    if (i < n2) {
        float2 v = ((const float2*)src)[i];
        ((uint32_t*)dst)[i] = pack_h2(v.x, v.y);
    }
}
__global__ void conv_split(const float* __restrict__ src,
                           __half* __restrict__ h, __half* __restrict__ l, int n2)
{
    int i = blockIdx.x * blockDim.x + threadIdx.x;
    if (i < n2) {
        float2 v = ((const float2*)src)[i];
        uint32_t hh, ll;
        split16(v.x, v.y, hh, ll);
        ((uint32_t*)h)[i] = hh;
        ((uint32_t*)l)[i] = ll;
    }
}

// ---------------------------------------------------------------------------
// fp16 split GEMM, NT: out[m,j] = sum_k A[m,k]*W[j,k],  A fp16, W hi+lo.
// BM=BN=128, BK=32, 256 thr (2x4 warps), 3-stage cp.async, ldmatrix frags.
// ---------------------------------------------------------------------------
#define PADK 20
#define G_A  (128*PADK)               // u32 per array
#define G_SU (3*G_A)                  // A, Wh, Wl
#define GEMM_SMEM (3*G_SU*4)          // 92160 B

template<int MODE>
__global__ void __launch_bounds__(256, 2) gemm_mma(
    const __half* __restrict__ A, const __half* __restrict__ W_h,
    const __half* __restrict__ W_l, const float* __restrict__ bias,
    float* __restrict__ out)
{
    extern __shared__ uint32_t sm[];

    const int tid  = threadIdx.x;
    const int lane = tid & 31;
    const int warp = tid >> 5;
    const int wm   = warp >> 2;
    const int wn   = warp & 3;
    const int rowBase = blockIdx.y * 128;
    const int colBase = blockIdx.x * 128;

    const int lrow8 = lane & 7;
    const int lsel  = lane >> 3;
    const int a_row = (lsel & 1)*8 + lrow8;
    const int a_col = (lsel >> 1)*4;
    const int b_row = (lsel >> 1)*8 + lrow8;
    const int b_col = (lsel & 1)*4;

    const int lr = tid >> 1, lh = tid & 1;
    const __half* pA  = A   + (size_t)(rowBase + lr) * Cdim + lh*16;
    const __half* pWh = W_h + (size_t)(colBase + lr) * Cdim + lh*16;
    const __half* pWl = W_l + (size_t)(colBase + lr) * Cdim + lh*16;
    const uint32_t dRow = (uint32_t)(lr*PADK + lh*8) * 4;
    const uint32_t sbase = smem_a(sm);

    float acc[4][4][4];
#pragma unroll
    for (int mt = 0; mt < 4; mt++)
#pragma unroll
        for (int nt = 0; nt < 4; nt++)
#pragma unroll
            for (int i = 0; i < 4; i++) acc[mt][nt][i] = 0.f;

#define G_ISSUE(s, k0)                                                  \
    do {                                                                \
        uint32_t b0 = sbase + (uint32_t)(s)*G_SU*4 + dRow;              \
        cp16(b0,              pA  + (k0)); cp16(b0 + 16,             pA  + (k0) + 8); \
        cp16(b0 + G_A*4,      pWh + (k0)); cp16(b0 + G_A*4 + 16,     pWh + (k0) + 8); \
        cp16(b0 + 2*G_A*4,    pWl + (k0)); cp16(b0 + 2*G_A*4 + 16,   pWl + (k0) + 8); \
    } while (0)

    G_ISSUE(0, 0);  CP_COMMIT();
    G_ISSUE(1, 32); CP_COMMIT();

    const int NIT = Cdim / 32;
    for (int it = 0; it < NIT; it++) {
        if (it + 1 < NIT) cp_wait<1>(); else cp_wait<0>();
        __syncthreads();
        if (it + 2 < NIT) { G_ISSUE((it+2)%3, (it+2)*32); CP_COMMIT(); }

        const int s = it % 3;
        const uint32_t Abyte  = sbase + (uint32_t)(s*G_SU)*4;
        const uint32_t Whbyte = Abyte + G_A*4;
        const uint32_t Wlbyte = Abyte + 2*G_A*4;

#pragma unroll
        for (int ks = 0; ks < 2; ks++) {
            uint32_t fa[4][4];
#pragma unroll
            for (int mt = 0; mt < 4; mt++)
                ldsm_x4(fa[mt], Abyte + (uint32_t)(((wm*64 + mt*16 + a_row)*PADK) + ks*8 + a_col)*4);
#pragma unroll
            for (int pr = 0; pr < 2; pr++) {
                uint32_t wh4[4], wl4[4];
                const uint32_t wofs = (uint32_t)(((wn*32 + pr*16 + b_row)*PADK) + ks*8 + b_col)*4;
                ldsm_x4(wh4, Whbyte + wofs);
                ldsm_x4(wl4, Wlbyte + wofs);
#pragma unroll
                for (int mt = 0; mt < 4; mt++) {
                    mma_f16(acc[mt][2*pr],   fa[mt], wh4);
                    mma_f16(acc[mt][2*pr],   fa[mt], wl4);
                    mma_f16(acc[mt][2*pr+1], fa[mt], wh4 + 2);
                    mma_f16(acc[mt][2*pr+1], fa[mt], wl4 + 2);
                }
            }
        }
    }
#undef G_ISSUE

    // epilogue
#pragma unroll
    for (int mt = 0; mt < 4; mt++) {
#pragma unroll
        for (int nt = 0; nt < 4; nt++) {
            const int r0 = rowBase + wm*64 + mt*16 + (lane >> 2);
            const int cc = colBase + wn*32 + nt*8 + 2*(lane & 3);
            if (MODE == 1) {
                float b0 = bias[cc], b1 = bias[cc+1];
                *(float2*)(out + (size_t)r0*Cdim + cc) =
                    make_float2(acc[mt][nt][0] + b0, acc[mt][nt][1] + b1);
                *(float2*)(out + (size_t)(r0+8)*Cdim + cc) =
                    make_float2(acc[mt][nt][2] + b0, acc[mt][nt][3] + b1);
            } else {
#pragma unroll
                for (int half_ = 0; half_ < 2; half_++) {
                    const int m  = r0 + half_*8;
                    const float v0 = acc[mt][nt][half_*2 + 0];
                    const float v1 = acc[mt][nt][half_*2 + 1];
                    const int bb = m >> 11, n = m & (Nseq-1);
                    const int which = cc >> 10, c = cc & (Cdim-1);
                    const int hh = c >> 6, d = c & 63;
                    const size_t bh = (size_t)bb*Hh + hh;
                    if (which == 0) {
                        const size_t idx = (bh*Nseq + n)*HDd + d;
                        *(uint32_t*)(g_qa + idx) = pack_h2(v0*SCALE, v1*SCALE);
                    } else if (which == 1) {
                        const size_t idx = (bh*Nseq + n)*HDd + d;
                        *(uint32_t*)(g_kh + idx) = pack_h2(v0, v1);
                    } else {
                        const size_t idx = (bh*HDd + d)*Nseq + n;  // transposed
                        __half2 hv = __floats2half2_rn(v0, v1);
                        g_vth[idx]        = hv.x;
                        g_vth[idx + Nseq] = hv.y;
                    }
                }
            }
        }
    }
}

// ---------------------------------------------------------------------------
// Flash attention, fp16 (Q/K/V/P all fp16 single-term), 3-stage cp.async,
// ldmatrix fragments, ALiBi prefetched into registers.
// Grid: (N/128, B*H). Block: 256 (8 warps).
// ---------------------------------------------------------------------------
#define PADA 36
#define A_KV (64*PADA)                 // u32 per K/V array
#define A_SU (2*A_KV + 64)             // K, V, mask
#define ATTN_SMEM (3*A_SU*4)           // 56064 B

__global__ void __launch_bounds__(256, 2) attn_mma(
    const float* __restrict__ alibi, const int* __restrict__ pmask)
{
    extern __shared__ uint32_t sm[];

    const int tid  = threadIdx.x;
    const int lane = tid & 31;
    const int warp = tid >> 5;
    const int bh   = blockIdx.y;
    const int b    = bh >> 4;
    const int h    = bh & 15;
    const int q0   = blockIdx.x * 128;

    const int r0 = warp*16 + (lane >> 2);
    const int c2 = 2*(lane & 3);

    const int lrow8 = lane & 7;
    const int lsel  = lane >> 3;
    const int b_row = (lsel >> 1)*8 + lrow8;
    const int b_col = (lsel & 1)*4;

    // Q fragments (fp16, register-resident)
    uint32_t qa[4][4];
    {
        const __half* qb = g_qa + ((size_t)bh*Nseq + q0 + r0)*HDd;
#pragma unroll
        for (int ks = 0; ks < 4; ks++) {
            qa[ks][0] = *(const uint32_t*)(qb + ks*16 + c2);
            qa[ks][1] = *(const uint32_t*)(qb + 8*HDd + ks*16 + c2);
            qa[ks][2] = *(const uint32_t*)(qb + ks*16 + c2 + 8);
            qa[ks][3] = *(const uint32_t*)(qb + 8*HDd + ks*16 + c2 + 8);
        }
    }

    float o[8][4];
#pragma unroll
    for (int dt = 0; dt < 8; dt++)
#pragma unroll
        for (int i = 0; i < 4; i++) o[dt][i] = 0.f;
    float m0 = -1e30f, m1 = -1e30f, l0 = 0.f, l1 = 0.f;

    const __half* kh_g = g_kh  + (size_t)bh*Nseq*HDd;
    const __half* vh_g = g_vth + (size_t)bh*HDd*Nseq;
    const float*  ab   = alibi + ((size_t)bh*Nseq + q0)*Nseq;
    const int*    pm   = pmask + (size_t)b*Nseq;

    const uint32_t sbase = smem_a(sm);
    const int sr = tid >> 2;
    const int sq = tid & 3;

#define A_ISSUE(s, k0)                                                        \
    do {                                                                      \
        const uint32_t st = sbase + (uint32_t)(s)*A_SU*4;                     \
        const uint32_t rb = (uint32_t)(sr*PADA + sq*8)*4;                     \
        const __half* k_h = kh_g + (size_t)((k0) + sr)*HDd + sq*16;           \
        const __half* v_h = vh_g + (size_t)sr*Nseq + (k0) + sq*16;            \
        cp16(st + rb,            k_h);  cp16(st + rb + 16,            k_h + 8); \
        cp16(st + A_KV*4 + rb,   v_h);  cp16(st + A_KV*4 + rb + 16,   v_h + 8); \
        if (tid < 16)                                                         \
            cp16(st + 2*A_KV*4 + tid*16, pm + (k0) + tid*4);                  \
    } while (0)

    A_ISSUE(0, 0);  CP_COMMIT();
    A_ISSUE(1, 64); CP_COMMIT();

    const int NIT = Nseq / 64;
    for (int it = 0; it < NIT; it++) {
        if (it + 1 < NIT) cp_wait<1>(); else cp_wait<0>();
        __syncthreads();
        if (it + 2 < NIT) { A_ISSUE((it+2)%3, (it+2)*64); CP_COMMIT(); }

        const int k0 = it * 64;
        const int s  = it % 3;
        const uint32_t Khb = sbase + (uint32_t)(s*A_SU)*4;
        const uint32_t Vhb = Khb + A_KV*4;
        const int* Mk = (const int*)(sm + s*A_SU + 2*A_KV);

        // Prefetch ALiBi into registers; consumed after the S-mma chain.
        float2 ali0[8], ali1[8];
#pragma unroll
        for (int nt = 0; nt < 8; nt++) {
            const int kc = nt*8 + c2;
            ali0[nt] = *(const float2*)(ab + (size_t)r0*Nseq + k0 + kc);
            ali1[nt] = *(const float2*)(ab + (size_t)(r0+8)*Nseq + k0 + kc);
        }

        // S = Q K^T
        float sacc[8][4];
#pragma unroll
        for (int nt = 0; nt < 8; nt++)
#pragma unroll
            for (int i = 0; i < 4; i++) sacc[nt][i] = 0.f;
#pragma unroll
        for (int ks = 0; ks < 4; ks++) {
#pragma unroll
            for (int pr = 0; pr < 4; pr++) {
                uint32_t kh4[4];
                ldsm_x4(kh4, Khb + (uint32_t)(((pr*16 + b_row)*PADA) + ks*8 + b_col)*4);
                mma_f16(sacc[2*pr],   qa[ks], kh4);
                mma_f16(sacc[2*pr+1], qa[ks], kh4 + 2);
            }
        }

        // + alibi + mask
#pragma unroll
        for (int nt = 0; nt < 8; nt++) {
            const int kc = nt*8 + c2;
            const float mk0 = Mk[kc]   ? -1e30f : 0.f;
            const float mk1 = Mk[kc+1] ? -1e30f : 0.f;
            sacc[nt][0] += ali0[nt].x + mk0;  sacc[nt][1] += ali0[nt].y + mk1;
            sacc[nt][2] += ali1[nt].x + mk0;  sacc[nt][3] += ali1[nt].y + mk1;
        }

        // online softmax (rows r0, r0+8)
        float mx0 = -1e30f, mx1 = -1e30f;
#pragma unroll
        for (int nt = 0; nt < 8; nt++) {
            mx0 = fmaxf(mx0, fmaxf(sacc[nt][0], sacc[nt][1]));
            mx1 = fmaxf(mx1, fmaxf(sacc[nt][2], sacc[nt][3]));
        }
        mx0 = fmaxf(mx0, __shfl_xor_sync(0xffffffffu, mx0, 1));
        mx0 = fmaxf(mx0, __shfl_xor_sync(0xffffffffu, mx0, 2));
        mx1 = fmaxf(mx1, __shfl_xor_sync(0xffffffffu, mx1, 1));
        mx1 = fmaxf(mx1, __shfl_xor_sync(0xffffffffu, mx1, 2));

        const float mn0 = fmaxf(m0, mx0), mn1 = fmaxf(m1, mx1);
        const float cr0 = __expf(m0 - mn0), cr1 = __expf(m1 - mn1);
        float ls0 = 0.f, ls1 = 0.f;
#pragma unroll
        for (int nt = 0; nt < 8; nt++) {
            sacc[nt][0] = __expf(sacc[nt][0] - mn0);
            sacc[nt][1] = __expf(sacc[nt][1] - mn0);
            sacc[nt][2] = __expf(sacc[nt][2] - mn1);
            sacc[nt][3] = __expf(sacc[nt][3] - mn1);
            ls0 += sacc[nt][0] + sacc[nt][1];
            ls1 += sacc[nt][2] + sacc[nt][3];
        }
        ls0 += __shfl_xor_sync(0xffffffffu, ls0, 1);
        ls0 += __shfl_xor_sync(0xffffffffu, ls0, 2);
        ls1 += __shfl_xor_sync(0xffffffffu, ls1, 1);
        ls1 += __shfl_xor_sync(0xffffffffu, ls1, 2);
        l0 = l0*cr0 + ls0;  l1 = l1*cr1 + ls1;
        m0 = mn0;           m1 = mn1;

#pragma unroll
        for (int dt = 0; dt < 8; dt++) {
            o[dt][0] *= cr0; o[dt][1] *= cr0;
            o[dt][2] *= cr1; o[dt][3] *= cr1;
        }

        // O += P V   (P rounded to fp16)
#pragma unroll
        for (int pk = 0; pk < 4; pk++) {
            uint32_t pa[4];
            pa[0] = pack_h2(sacc[2*pk][0],   sacc[2*pk][1]);
            pa[1] = pack_h2(sacc[2*pk][2],   sacc[2*pk][3]);
            pa[2] = pack_h2(sacc[2*pk+1][0], sacc[2*pk+1][1]);
            pa[3] = pack_h2(sacc[2*pk+1][2], sacc[2*pk+1][3]);
#pragma unroll
            for (int pr = 0; pr < 4; pr++) {
                uint32_t vh4[4];
                ldsm_x4(vh4, Vhb + (uint32_t)(((pr*16 + b_row)*PADA) + pk*8 + b_col)*4);
                mma_f16(o[2*pr],   pa, vh4);
                mma_f16(o[2*pr+1], pa, vh4 + 2);
            }
        }
    }
#undef A_ISSUE

    // finalize: fp16 output (feeds proj GEMM A-side)
    const float inv0 = (l0 > 0.f) ? (1.f/l0) : 0.f;
    const float inv1 = (l1 > 0.f) ? (1.f/l1) : 0.f;
    const size_t i0 = ((size_t)b*Nseq + q0 + r0)*Cdim + h*HDd;
    const size_t i1 = i0 + (size_t)8*Cdim;
#pragma unroll
    for (int dt = 0; dt < 8; dt++) {
        *(uint32_t*)(g_ao + i0 + dt*8 + c2) = pack_h2(o[dt][0]*inv0, o[dt][1]*inv0);
        *(uint32_t*)(g_ao + i1 + dt*8 + c2) = pack_h2(o[dt][2]*inv1, o[dt][3]*inv1);
    }
}

// ---------------------------------------------------------------------------
extern "C" void kernel_launch(void* const* d_in, const int* in_sizes, int n_in,
                              void* d_out, int out_size)
{
    const float* x      = (const float*)d_in[0];
    const int*   pmask  = (const int*)d_in[1];
    const float* alibi  = (const float*)d_in[2];
    const float* qkv_w  = (const float*)d_in[3];
    const float* proj_w = (const float*)d_in[4];
    const float* proj_b = (const float*)d_in[5];
    float*       out    = (float*)d_out;

    cudaFuncSetAttribute(gemm_mma<0>, cudaFuncAttributeMaxDynamicSharedMemorySize, GEMM_SMEM);
    cudaFuncSetAttribute(gemm_mma<1>, cudaFuncAttributeMaxDynamicSharedMemorySize, GEMM_SMEM);
    cudaFuncSetAttribute(attn_mma,    cudaFuncAttributeMaxDynamicSharedMemorySize, ATTN_SMEM);

    __half *xa, *qwh, *qwl, *pwh, *pwl, *ao;
    cudaGetSymbolAddress((void**)&xa,  g_xa);
    cudaGetSymbolAddress((void**)&qwh, g_qwh); cudaGetSymbolAddress((void**)&qwl, g_qwl);
    cudaGetSymbolAddress((void**)&pwh, g_pwh); cudaGetSymbolAddress((void**)&pwl, g_pwl);
    cudaGetSymbolAddress((void**)&ao,  g_ao);

    // 0) pre-convert
    conv_half <<<(Mrows*Cdim/2 + 255)/256, 256>>>(x, xa, Mrows*Cdim/2);
    conv_split<<<(3*Cdim*Cdim/2 + 255)/256, 256>>>(qkv_w, qwh, qwl, 3*Cdim*Cdim/2);
    conv_split<<<(Cdim*Cdim/2 + 255)/256, 256>>>(proj_w,  pwh, pwl, Cdim*Cdim/2);

    // 1) QKV projection
    gemm_mma<0><<<dim3(24, 32), 256, GEMM_SMEM>>>(xa, qwh, qwl, nullptr, nullptr);

    // 2) attention
    attn_mma<<<dim3(Nseq/128, Bq*Hh), 256, ATTN_SMEM>>>(alibi, pmask);

    // 3) output projection
    gemm_mma<1><<<dim3(8, 32), 256, GEMM_SMEM>>>(ao, pwh, pwl, proj_b, out);
}

// round 9
// speedup vs baseline: 3.0434x; 1.2902x over previous
#include <cuda_runtime.h>
#include <cuda_fp16.h>
#include <cstdint>

#define Bq    2
#define Nseq  2048
#define Cdim  1024
#define Hh    16
#define HDd   64
#define SCALE 0.125f
#define Mrows (Bq*Nseq)

// ---------------- device scratch ----------------
__device__ __half g_qa [(size_t)Bq*Hh*Nseq*HDd];   // Q fp16 (pre-scaled), [bh][n][d]
__device__ __half g_kh [(size_t)Bq*Hh*Nseq*HDd];   // K fp16 [bh][key][dim]
__device__ __half g_vth[(size_t)Bq*Hh*HDd*Nseq];   // V^T fp16 [bh][dim][key]
__device__ __half g_xa [(size_t)Mrows*Cdim];       // x fp16
__device__ __half g_qwh[(size_t)3*Cdim*Cdim];      // qkv_w fp16
__device__ __half g_pwh[(size_t)Cdim*Cdim];        // proj_w fp16
__device__ __half g_ao [(size_t)Mrows*Cdim];       // attn out fp16

// ---------------- helpers ----------------
__device__ __forceinline__ void mma_f16(float* d, const uint32_t* a, const uint32_t* b)
{
    asm volatile(
        "mma.sync.aligned.m16n8k16.row.col.f32.f16.f16.f32 "
        "{%0,%1,%2,%3}, {%4,%5,%6,%7}, {%8,%9}, {%0,%1,%2,%3};"
        : "+f"(d[0]), "+f"(d[1]), "+f"(d[2]), "+f"(d[3])
        : "r"(a[0]), "r"(a[1]), "r"(a[2]), "r"(a[3]), "r"(b[0]), "r"(b[1]));
}

__device__ __forceinline__ void ldsm_x4(uint32_t* r, uint32_t saddr)
{
    asm volatile(
        "ldmatrix.sync.aligned.m8n8.x4.shared.b16 {%0,%1,%2,%3}, [%4];"
        : "=r"(r[0]), "=r"(r[1]), "=r"(r[2]), "=r"(r[3]) : "r"(saddr));
}

__device__ __forceinline__ uint32_t pack_h2(float x, float y)
{
    __half2 h = __floats2half2_rn(x, y);
    return *reinterpret_cast<uint32_t*>(&h);
}

__device__ __forceinline__ uint32_t smem_a(const void* p)
{
    return (uint32_t)__cvta_generic_to_shared(p);
}
__device__ __forceinline__ void cp16(uint32_t dst, const void* src)
{
    asm volatile("cp.async.cg.shared.global [%0], [%1], 16;\n" :: "r"(dst), "l"(src));
}
#define CP_COMMIT() asm volatile("cp.async.commit_group;\n")
template<int N> __device__ __forceinline__ void cp_wait()
{
    asm volatile("cp.async.wait_group %0;\n" :: "n"(N));
}

// ---------------- prep: one fused fp32->fp16 convert for x, qkv_w, proj_w ----
#define NX2 (Mrows*Cdim/2)
#define NQ2 (3*Cdim*Cdim/2)
#define NP2 (Cdim*Cdim/2)

__global__ void conv_all(const float* __restrict__ x,  const float* __restrict__ qw,
                         const float* __restrict__ pw, __half* __restrict__ xa,
                         __half* __restrict__ qwh,     __half* __restrict__ pwh)
{
    int i = blockIdx.x * blockDim.x + threadIdx.x;
    if (i < NX2) {
        float2 v = ((const float2*)x)[i];
        ((uint32_t*)xa)[i] = pack_h2(v.x, v.y);
    } else if (i < NX2 + NQ2) {
        int j = i - NX2;
        float2 v = ((const float2*)qw)[j];
        ((uint32_t*)qwh)[j] = pack_h2(v.x, v.y);
    } else if (i < NX2 + NQ2 + NP2) {
        int j = i - NX2 - NQ2;
        float2 v = ((const float2*)pw)[j];
        ((uint32_t*)pwh)[j] = pack_h2(v.x, v.y);
    }
}

// ---------------------------------------------------------------------------
// fp16 GEMM, NT: out[m,j] = sum_k A[m,k]*W[j,k] (both single fp16).
// BM=BN=128, BK=32, 256 thr (2x4 warps), 3-stage cp.async, ldmatrix frags.
// ---------------------------------------------------------------------------
#define PADK 20
#define G_A  (128*PADK)               // u32 per array
#define G_SU (2*G_A)                  // A, W
#define GEMM_SMEM (3*G_SU*4)          // 61440 B

template<int MODE>
__global__ void __launch_bounds__(256, 2) gemm_mma(
    const __half* __restrict__ A, const __half* __restrict__ W_h,
    const float* __restrict__ bias, float* __restrict__ out)
{
    extern __shared__ uint32_t sm[];

    const int tid  = threadIdx.x;
    const int lane = tid & 31;
    const int warp = tid >> 5;
    const int wm   = warp >> 2;
    const int wn   = warp & 3;
    const int rowBase = blockIdx.y * 128;
    const int colBase = blockIdx.x * 128;

    const int lrow8 = lane & 7;
    const int lsel  = lane >> 3;
    const int a_row = (lsel & 1)*8 + lrow8;
    const int a_col = (lsel >> 1)*4;
    const int b_row = (lsel >> 1)*8 + lrow8;
    const int b_col = (lsel & 1)*4;

    const int lr = tid >> 1, lh = tid & 1;
    const __half* pA  = A   + (size_t)(rowBase + lr) * Cdim + lh*16;
    const __half* pWh = W_h + (size_t)(colBase + lr) * Cdim + lh*16;
    const uint32_t dRow = (uint32_t)(lr*PADK + lh*8) * 4;
    const uint32_t sbase = smem_a(sm);

    float acc[4][4][4];
#pragma unroll
    for (int mt = 0; mt < 4; mt++)
#pragma unroll
        for (int nt = 0; nt < 4; nt++)
#pragma unroll
            for (int i = 0; i < 4; i++) acc[mt][nt][i] = 0.f;

#define G_ISSUE(s, k0)                                                  \
    do {                                                                \
        uint32_t b0 = sbase + (uint32_t)(s)*G_SU*4 + dRow;              \
        cp16(b0,          pA  + (k0)); cp16(b0 + 16,         pA  + (k0) + 8); \
        cp16(b0 + G_A*4,  pWh + (k0)); cp16(b0 + G_A*4 + 16, pWh + (k0) + 8); \
    } while (0)

    G_ISSUE(0, 0);  CP_COMMIT();
    G_ISSUE(1, 32); CP_COMMIT();

    const int NIT = Cdim / 32;
    for (int it = 0; it < NIT; it++) {
        if (it + 1 < NIT) cp_wait<1>(); else cp_wait<0>();
        __syncthreads();
        if (it + 2 < NIT) { G_ISSUE((it+2)%3, (it+2)*32); CP_COMMIT(); }

        const int s = it % 3;
        const uint32_t Abyte  = sbase + (uint32_t)(s*G_SU)*4;
        const uint32_t Whbyte = Abyte + G_A*4;

#pragma unroll
        for (int ks = 0; ks < 2; ks++) {
            uint32_t fa[4][4];
#pragma unroll
            for (int mt = 0; mt < 4; mt++)
                ldsm_x4(fa[mt], Abyte + (uint32_t)(((wm*64 + mt*16 + a_row)*PADK) + ks*8 + a_col)*4);
#pragma unroll
            for (int pr = 0; pr < 2; pr++) {
                uint32_t wh4[4];
                ldsm_x4(wh4, Whbyte + (uint32_t)(((wn*32 + pr*16 + b_row)*PADK) + ks*8 + b_col)*4);
#pragma unroll
                for (int mt = 0; mt < 4; mt++) {
                    mma_f16(acc[mt][2*pr],   fa[mt], wh4);
                    mma_f16(acc[mt][2*pr+1], fa[mt], wh4 + 2);
                }
            }
        }
    }
#undef G_ISSUE

    // epilogue
#pragma unroll
    for (int mt = 0; mt < 4; mt++) {
#pragma unroll
        for (int nt = 0; nt < 4; nt++) {
            const int r0 = rowBase + wm*64 + mt*16 + (lane >> 2);
            const int cc = colBase + wn*32 + nt*8 + 2*(lane & 3);
            if (MODE == 1) {
                float b0 = bias[cc], b1 = bias[cc+1];
                *(float2*)(out + (size_t)r0*Cdim + cc) =
                    make_float2(acc[mt][nt][0] + b0, acc[mt][nt][1] + b1);
                *(float2*)(out + (size_t)(r0+8)*Cdim + cc) =
                    make_float2(acc[mt][nt][2] + b0, acc[mt][nt][3] + b1);
            } else {
#pragma unroll
                for (int half_ = 0; half_ < 2; half_++) {
                    const int m  = r0 + half_*8;
                    const float v0 = acc[mt][nt][half_*2 + 0];
                    const float v1 = acc[mt][nt][half_*2 + 1];
                    const int bb = m >> 11, n = m & (Nseq-1);
                    const int which = cc >> 10, c = cc & (Cdim-1);
                    const int hh = c >> 6, d = c & 63;
                    const size_t bh = (size_t)bb*Hh + hh;
                    if (which == 0) {
                        const size_t idx = (bh*Nseq + n)*HDd + d;
                        *(uint32_t*)(g_qa + idx) = pack_h2(v0*SCALE, v1*SCALE);
                    } else if (which == 1) {
                        const size_t idx = (bh*Nseq + n)*HDd + d;
                        *(uint32_t*)(g_kh + idx) = pack_h2(v0, v1);
                    } else {
                        const size_t idx = (bh*HDd + d)*Nseq + n;  // transposed
                        __half2 hv = __floats2half2_rn(v0, v1);
                        g_vth[idx]        = hv.x;
                        g_vth[idx + Nseq] = hv.y;
                    }
                }
            }
        }
    }
}

// ---------------------------------------------------------------------------
// Flash attention, fp16, 3-stage cp.async, ldmatrix, reg-prefetched ALiBi.
// Grid: (N/128, B*H). Block: 256 (8 warps).
// ---------------------------------------------------------------------------
#define PADA 36
#define A_KV (64*PADA)                 // u32 per K/V array
#define A_SU (2*A_KV + 64)             // K, V, mask
#define ATTN_SMEM (3*A_SU*4)           // 56064 B

__global__ void __launch_bounds__(256, 2) attn_mma(
    const float* __restrict__ alibi, const int* __restrict__ pmask)
{
    extern __shared__ uint32_t sm[];

    const int tid  = threadIdx.x;
    const int lane = tid & 31;
    const int warp = tid >> 5;
    const int bh   = blockIdx.y;
    const int b    = bh >> 4;
    const int h    = bh & 15;
    const int q0   = blockIdx.x * 128;

    const int r0 = warp*16 + (lane >> 2);
    const int c2 = 2*(lane & 3);

    const int lrow8 = lane & 7;
    const int lsel  = lane >> 3;
    const int b_row = (lsel >> 1)*8 + lrow8;
    const int b_col = (lsel & 1)*4;

    // Q fragments (fp16, register-resident)
    uint32_t qa[4][4];
    {
        const __half* qb = g_qa + ((size_t)bh*Nseq + q0 + r0)*HDd;
#pragma unroll
        for (int ks = 0; ks < 4; ks++) {
            qa[ks][0] = *(const uint32_t*)(qb + ks*16 + c2);
            qa[ks][1] = *(const uint32_t*)(qb + 8*HDd + ks*16 + c2);
            qa[ks][2] = *(const uint32_t*)(qb + ks*16 + c2 + 8);
            qa[ks][3] = *(const uint32_t*)(qb + 8*HDd + ks*16 + c2 + 8);
        }
    }

    float o[8][4];
#pragma unroll
    for (int dt = 0; dt < 8; dt++)
#pragma unroll
        for (int i = 0; i < 4; i++) o[dt][i] = 0.f;
    float m0 = -1e30f, m1 = -1e30f, l0 = 0.f, l1 = 0.f;

    const __half* kh_g = g_kh  + (size_t)bh*Nseq*HDd;
    const __half* vh_g = g_vth + (size_t)bh*HDd*Nseq;
    const float*  ab   = alibi + ((size_t)bh*Nseq + q0)*Nseq;
    const int*    pm   = pmask + (size_t)b*Nseq;

    const uint32_t sbase = smem_a(sm);
    const int sr = tid >> 2;
    const int sq = tid & 3;

#define A_ISSUE(s, k0)                                                        \
    do {                                                                      \
        const uint32_t st = sbase + (uint32_t)(s)*A_SU*4;                     \
        const uint32_t rb = (uint32_t)(sr*PADA + sq*8)*4;                     \
        const __half* k_h = kh_g + (size_t)((k0) + sr)*HDd + sq*16;           \
        const __half* v_h = vh_g + (size_t)sr*Nseq + (k0) + sq*16;            \
        cp16(st + rb,            k_h);  cp16(st + rb + 16,            k_h + 8); \
        cp16(st + A_KV*4 + rb,   v_h);  cp16(st + A_KV*4 + rb + 16,   v_h + 8); \
        if (tid < 16)                                                         \
            cp16(st + 2*A_KV*4 + tid*16, pm + (k0) + tid*4);                  \
    } while (0)

    A_ISSUE(0, 0);  CP_COMMIT();
    A_ISSUE(1, 64); CP_COMMIT();

    const int NIT = Nseq / 64;
    for (int it = 0; it < NIT; it++) {
        if (it + 1 < NIT) cp_wait<1>(); else cp_wait<0>();
        __syncthreads();
        if (it + 2 < NIT) { A_ISSUE((it+2)%3, (it+2)*64); CP_COMMIT(); }

        const int k0 = it * 64;
        const int s  = it % 3;
        const uint32_t Khb = sbase + (uint32_t)(s*A_SU)*4;
        const uint32_t Vhb = Khb + A_KV*4;
        const int* Mk = (const int*)(sm + s*A_SU + 2*A_KV);

        // Prefetch ALiBi into registers; consumed after the S-mma chain.
        float2 ali0[8], ali1[8];
#pragma unroll
        for (int nt = 0; nt < 8; nt++) {
            const int kc = nt*8 + c2;
            ali0[nt] = *(const float2*)(ab + (size_t)r0*Nseq + k0 + kc);
            ali1[nt] = *(const float2*)(ab + (size_t)(r0+8)*Nseq + k0 + kc);
        }

        // S = Q K^T
        float sacc[8][4];
#pragma unroll
        for (int nt = 0; nt < 8; nt++)
#pragma unroll
            for (int i = 0; i < 4; i++) sacc[nt][i] = 0.f;
#pragma unroll
        for (int ks = 0; ks < 4; ks++) {
#pragma unroll
            for (int pr = 0; pr < 4; pr++) {
                uint32_t kh4[4];
                ldsm_x4(kh4, Khb + (uint32_t)(((pr*16 + b_row)*PADA) + ks*8 + b_col)*4);
                mma_f16(sacc[2*pr],   qa[ks], kh4);
                mma_f16(sacc[2*pr+1], qa[ks], kh4 + 2);
            }
        }

        // + alibi + mask
#pragma unroll
        for (int nt = 0; nt < 8; nt++) {
            const int kc = nt*8 + c2;
            const float mk0 = Mk[kc]   ? -1e30f : 0.f;
            const float mk1 = Mk[kc+1] ? -1e30f : 0.f;
            sacc[nt][0] += ali0[nt].x + mk0;  sacc[nt][1] += ali0[nt].y + mk1;
            sacc[nt][2] += ali1[nt].x + mk0;  sacc[nt][3] += ali1[nt].y + mk1;
        }

        // online softmax (rows r0, r0+8)
        float mx0 = -1e30f, mx1 = -1e30f;
#pragma unroll
        for (int nt = 0; nt < 8; nt++) {
            mx0 = fmaxf(mx0, fmaxf(sacc[nt][0], sacc[nt][1]));
            mx1 = fmaxf(mx1, fmaxf(sacc[nt][2], sacc[nt][3]));
        }
        mx0 = fmaxf(mx0, __shfl_xor_sync(0xffffffffu, mx0, 1));
        mx0 = fmaxf(mx0, __shfl_xor_sync(0xffffffffu, mx0, 2));
        mx1 = fmaxf(mx1, __shfl_xor_sync(0xffffffffu, mx1, 1));
        mx1 = fmaxf(mx1, __shfl_xor_sync(0xffffffffu, mx1, 2));

        const float mn0 = fmaxf(m0, mx0), mn1 = fmaxf(m1, mx1);
        const float cr0 = __expf(m0 - mn0), cr1 = __expf(m1 - mn1);
        float ls0 = 0.f, ls1 = 0.f;
#pragma unroll
        for (int nt = 0; nt < 8; nt++) {
            sacc[nt][0] = __expf(sacc[nt][0] - mn0);
            sacc[nt][1] = __expf(sacc[nt][1] - mn0);
            sacc[nt][2] = __expf(sacc[nt][2] - mn1);
            sacc[nt][3] = __expf(sacc[nt][3] - mn1);
            ls0 += sacc[nt][0] + sacc[nt][1];
            ls1 += sacc[nt][2] + sacc[nt][3];
        }
        ls0 += __shfl_xor_sync(0xffffffffu, ls0, 1);
        ls0 += __shfl_xor_sync(0xffffffffu, ls0, 2);
        ls1 += __shfl_xor_sync(0xffffffffu, ls1, 1);
        ls1 += __shfl_xor_sync(0xffffffffu, ls1, 2);
        l0 = l0*cr0 + ls0;  l1 = l1*cr1 + ls1;
        m0 = mn0;           m1 = mn1;

#pragma unroll
        for (int dt = 0; dt < 8; dt++) {
            o[dt][0] *= cr0; o[dt][1] *= cr0;
            o[dt][2] *= cr1; o[dt][3] *= cr1;
        }

        // O += P V   (P rounded to fp16)
#pragma unroll
        for (int pk = 0; pk < 4; pk++) {
            uint32_t pa[4];
            pa[0] = pack_h2(sacc[2*pk][0],   sacc[2*pk][1]);
            pa[1] = pack_h2(sacc[2*pk][2],   sacc[2*pk][3]);
            pa[2] = pack_h2(sacc[2*pk+1][0], sacc[2*pk+1][1]);
            pa[3] = pack_h2(sacc[2*pk+1][2], sacc[2*pk+1][3]);
#pragma unroll
            for (int pr = 0; pr < 4; pr++) {
                uint32_t vh4[4];
                ldsm_x4(vh4, Vhb + (uint32_t)(((pr*16 + b_row)*PADA) + pk*8 + b_col)*4);
                mma_f16(o[2*pr],   pa, vh4);
                mma_f16(o[2*pr+1], pa, vh4 + 2);
            }
        }
    }
#undef A_ISSUE

    // finalize: fp16 output (feeds proj GEMM A-side)
    const float inv0 = (l0 > 0.f) ? (1.f/l0) : 0.f;
    const float inv1 = (l1 > 0.f) ? (1.f/l1) : 0.f;
    const size_t i0 = ((size_t)b*Nseq + q0 + r0)*Cdim + h*HDd;
    const size_t i1 = i0 + (size_t)8*Cdim;
#pragma unroll
    for (int dt = 0; dt < 8; dt++) {
        *(uint32_t*)(g_ao + i0 + dt*8 + c2) = pack_h2(o[dt][0]*inv0, o[dt][1]*inv0);
        *(uint32_t*)(g_ao + i1 + dt*8 + c2) = pack_h2(o[dt][2]*inv1, o[dt][3]*inv1);
    }
}

// ---------------------------------------------------------------------------
extern "C" void kernel_launch(void* const* d_in, const int* in_sizes, int n_in,
                              void* d_out, int out_size)
{
    const float* x      = (const float*)d_in[0];
    const int*   pmask  = (const int*)d_in[1];
    const float* alibi  = (const float*)d_in[2];
    const float* qkv_w  = (const float*)d_in[3];
    const float* proj_w = (const float*)d_in[4];
    const float* proj_b = (const float*)d_in[5];
    float*       out    = (float*)d_out;

    cudaFuncSetAttribute(gemm_mma<0>, cudaFuncAttributeMaxDynamicSharedMemorySize, GEMM_SMEM);
    cudaFuncSetAttribute(gemm_mma<1>, cudaFuncAttributeMaxDynamicSharedMemorySize, GEMM_SMEM);
    cudaFuncSetAttribute(attn_mma,    cudaFuncAttributeMaxDynamicSharedMemorySize, ATTN_SMEM);

    __half *xa, *qwh, *pwh, *ao;
    cudaGetSymbolAddress((void**)&xa,  g_xa);
    cudaGetSymbolAddress((void**)&qwh, g_qwh);
    cudaGetSymbolAddress((void**)&pwh, g_pwh);
    cudaGetSymbolAddress((void**)&ao,  g_ao);

    // 0) fused pre-convert (x, qkv_w, proj_w -> fp16)
    conv_all<<<(NX2 + NQ2 + NP2 + 255)/256, 256>>>(x, qkv_w, proj_w, xa, qwh, pwh);

    // 1) QKV projection
    gemm_mma<0><<<dim3(24, 32), 256, GEMM_SMEM>>>(xa, qwh, nullptr, nullptr);

    // 2) attention
    attn_mma<<<dim3(Nseq/128, Bq*Hh), 256, ATTN_SMEM>>>(alibi, pmask);

    // 3) output projection
    gemm_mma<1><<<dim3(8, 32), 256, GEMM_SMEM>>>(ao, pwh, proj_b, out);
}